// round 5
// baseline (speedup 1.0000x reference)
#include <cuda_runtime.h>
#include <cuda_bf16.h>
#include <math.h>
#include <stdint.h>

// ---------------- problem constants ----------------
constexpr int Bv = 8, Tv = 8, Hv = 56, Wv = 56, Cv = 192;
constexpr int NHv = 6, Lv = Hv * Wv;                // 3136
constexpr int HIDv = 4 * Cv;                        // 768
constexpr int Mv = Bv * Tv * Lv;                    // 200704 tokens
constexpr long MCl = (long)Mv * Cv;
constexpr float QSCALE = 0.17677669529663687f;      // 32^-0.5

// ---------------- device scratch ----------------
typedef __nv_bfloat16 bf16;
__device__ float g_qkv[(long)Mv * 576];
__device__ bf16 g_a_hi[MCl],  g_a_lo[MCl];            // LN-applied activations
__device__ bf16 g_osp_hi[MCl], g_osp_lo[MCl];
__device__ bf16 g_ot_hi[MCl],  g_ot_lo[MCl];
__device__ bf16 g_h_hi[(long)Mv * HIDv], g_h_lo[(long)Mv * HIDv];
__device__ bf16 g_whi[847872], g_wlo[847872];
__device__ float g_xt_fb[MCl];
__device__ float g_xsp_fb[MCl];

// weight offsets in g_whi/g_wlo
constexpr int WO_QKV = 0;            // 576x192
constexpr int WO_PSP = 110592;       // 192x192
constexpr int WO_PT  = 147456;       // 192x192
constexpr int WO_TF1 = 184320;       // 768x192
constexpr int WO_TF2 = 331776;       // 192x768
constexpr int WO_SF1 = 479232;       // 768x192
constexpr int WO_SF2 = 626688;       // 192x768
constexpr int WO_FUSE = 774144;      // 192x384

// ---------------- helpers ----------------
__device__ __forceinline__ uint32_t smem_u32(const void* p) {
    uint32_t a;
    asm("{ .reg .u64 t; cvta.to.shared.u64 t, %1; cvt.u32.u64 %0, t; }" : "=r"(a) : "l"(p));
    return a;
}

#define LDSM4(r, addr)                                                        \
    asm volatile("ldmatrix.sync.aligned.m8n8.x4.shared.b16 {%0,%1,%2,%3}, [%4];" \
        : "=r"((r)[0]), "=r"((r)[1]), "=r"((r)[2]), "=r"((r)[3]) : "r"(addr))

#define MMA_BF16(c, a, b0, b1)                                                \
    asm volatile("mma.sync.aligned.m16n8k16.row.col.f32.bf16.bf16.f32 "       \
        "{%0,%1,%2,%3},{%4,%5,%6,%7},{%8,%9},{%0,%1,%2,%3};"                  \
        : "+f"((c)[0]), "+f"((c)[1]), "+f"((c)[2]), "+f"((c)[3])              \
        : "r"((a)[0]), "r"((a)[1]), "r"((a)[2]), "r"((a)[3]), "r"(b0), "r"(b1))

__device__ __forceinline__ void split2(float x, float y, uint32_t& hp, uint32_t& lp) {
    asm("cvt.rn.bf16x2.f32 %0, %1, %2;" : "=r"(hp) : "f"(y), "f"(x));
    float rx = x - __uint_as_float(hp << 16);
    float ry = y - __uint_as_float(hp & 0xFFFF0000u);
    asm("cvt.rn.bf16x2.f32 %0, %1, %2;" : "=r"(lp) : "f"(ry), "f"(rx));
}

// convert float4 -> bf16 hi quad + lo quad, store 8B each (row stride 80B) [fuse path]
__device__ __forceinline__ void cvst80(char* hi, char* lo, int row, int colf, float4 v) {
    uint32_t off = row * 80 + colf * 2;
    uint32_t h01, l01, h23, l23;
    split2(v.x, v.y, h01, l01);
    split2(v.z, v.w, h23, l23);
    *reinterpret_cast<uint2*>(hi + off) = make_uint2(h01, h23);
    *reinterpret_cast<uint2*>(lo + off) = make_uint2(l01, l23);
}

// ---------------- mma.sync fused GEMM ----------------
// Y = epi( A @ W^T + bias ),  A given as preconverted bf16 hi/lo (AM=0)
// or fp32 concat [Af | Af2] converted in-loader (AM=2, fuse only).
// EM: 0 bias; 1 bias+qscale(cols<192); 2 bias+residual; 4 bias+GELU -> dual bf16 out
constexpr int STAGE = 30720;   // Ahi 0 | Alo 10240 | Bhi 20480 | Blo 25600 (80B rows)
constexpr int DSMEM = 2 * STAGE;

template <int KD, int AM, int EM>
__global__ void __launch_bounds__(256, 2)
mma_gemm(const bf16* __restrict__ Ahi, const bf16* __restrict__ Alo,
         const float* __restrict__ Af, const float* __restrict__ Af2,
         const bf16* __restrict__ Whi, const bf16* __restrict__ Wlo,
         const float* __restrict__ bias, const float* __restrict__ R,
         float* __restrict__ Y, bf16* __restrict__ Yhi, bf16* __restrict__ Ylo,
         int N) {
    extern __shared__ char sm[];
    const int tid = threadIdx.x;
    const long m0 = (long)blockIdx.x * 128;
    const int n0 = blockIdx.y * 64;
    constexpr int NS = KD / 32;

    // loader mapping
    const int ar = tid >> 1;                 // A row 0..127 (2 thr/row)
    const int ab = (tid & 1) * 16;           // bf16 elem offset (0|16) within 32-elem chunk
    const int br = tid >> 2;                 // B row 0..63 (4 thr/row)
    const int bb = (tid & 3) * 8;            // bf16 elem offset within chunk

    // staging regs
    uint4 rah[2], ral[2], rbh, rbl;          // AM=0 path
    float4 pa[4], pb[2];                     // AM=2 path (pb unused: B always preconv)

    auto gload = [&](int s) {
        const int kg = s * 32;
        if (AM == 0) {
            const bf16* pah = Ahi + (m0 + ar) * (long)KD + kg + ab;
            const bf16* pal = Alo + (m0 + ar) * (long)KD + kg + ab;
            rah[0] = *reinterpret_cast<const uint4*>(pah);
            rah[1] = *reinterpret_cast<const uint4*>(pah + 8);
            ral[0] = *reinterpret_cast<const uint4*>(pal);
            ral[1] = *reinterpret_cast<const uint4*>(pal + 8);
        } else {
#pragma unroll
            for (int j = 0; j < 4; j++) {
                int col = kg + (tid & 1) * 16 + j * 4;
                const float* src = (col < 192) ? Af + (m0 + ar) * 192 + col
                                               : Af2 + (m0 + ar) * 192 + (col - 192);
                pa[j] = *reinterpret_cast<const float4*>(src);
            }
        }
        const bf16* pwh = Whi + (long)(n0 + br) * KD + kg + bb;
        const bf16* pwl = Wlo + (long)(n0 + br) * KD + kg + bb;
        rbh = *reinterpret_cast<const uint4*>(pwh);
        rbl = *reinterpret_cast<const uint4*>(pwl);
    };
    auto sstore = [&](int buf) {
        char* base = sm + buf * STAGE;
        if (AM == 0) {
            *reinterpret_cast<uint4*>(base + ar * 80 + ab * 2) = rah[0];
            *reinterpret_cast<uint4*>(base + ar * 80 + ab * 2 + 16) = rah[1];
            *reinterpret_cast<uint4*>(base + 10240 + ar * 80 + ab * 2) = ral[0];
            *reinterpret_cast<uint4*>(base + 10240 + ar * 80 + ab * 2 + 16) = ral[1];
        } else {
#pragma unroll
            for (int j = 0; j < 4; j++)
                cvst80(base, base + 10240, ar, (tid & 1) * 16 + j * 4, pa[j]);
        }
        *reinterpret_cast<uint4*>(base + 20480 + br * 80 + bb * 2) = rbh;
        *reinterpret_cast<uint4*>(base + 25600 + br * 80 + bb * 2) = rbl;
    };

    // mma mapping: 8 warps = 4(M) x 2(N); warp tile 32x32
    const int l = tid & 31, wid = tid >> 5;
    const int wm = wid & 3, wn = wid >> 2;
    const int arow = wm * 32 + (l & 15);
    const int acol8 = (l >> 4) * 8;
    const int brow = wn * 32 + (l & 7) + ((l >> 4) << 3);
    const int bcol8 = ((l >> 3) & 1) * 8;
    const uint32_t smb = smem_u32(sm);

    float acc[2][4][4];
#pragma unroll
    for (int i = 0; i < 2; i++)
#pragma unroll
        for (int j = 0; j < 4; j++)
#pragma unroll
            for (int k = 0; k < 4; k++) acc[i][j][k] = 0.f;

    auto mmastage = [&](int buf) {
        const uint32_t base = smb + buf * STAGE;
#pragma unroll
        for (int kt = 0; kt < 2; kt++) {
            uint32_t ah[2][4], alr[2][4], bh[2][4], blr[2][4];
#pragma unroll
            for (int mt = 0; mt < 2; mt++) {
                uint32_t addr = base + (arow + mt * 16) * 80 + (kt * 16 + acol8) * 2;
                LDSM4(ah[mt], addr);
                LDSM4(alr[mt], addr + 10240);
            }
#pragma unroll
            for (int nt = 0; nt < 2; nt++) {
                uint32_t addr = base + 20480 + (brow + nt * 16) * 80 + (kt * 16 + bcol8) * 2;
                LDSM4(bh[nt], addr);
                LDSM4(blr[nt], addr + 5120);
            }
#pragma unroll
            for (int mt = 0; mt < 2; mt++)
#pragma unroll
                for (int nn = 0; nn < 4; nn++) {
                    const int nt = nn >> 1, jj = nn & 1;
                    MMA_BF16(acc[mt][nn], ah[mt], bh[nt][2 * jj], bh[nt][2 * jj + 1]);
                    MMA_BF16(acc[mt][nn], ah[mt], blr[nt][2 * jj], blr[nt][2 * jj + 1]);
                    MMA_BF16(acc[mt][nn], alr[mt], bh[nt][2 * jj], bh[nt][2 * jj + 1]);
                }
        }
    };

    gload(0); sstore(0);
    gload(1);
    __syncthreads();
    for (int s = 0; s < NS; s++) {
        mmastage(s & 1);
        __syncthreads();
        if (s + 1 < NS) {
            sstore((s + 1) & 1);
            if (s + 2 < NS) gload(s + 2);
            __syncthreads();
        }
    }

    // register epilogue
    const int g = l >> 2, tg = l & 3;
#pragma unroll
    for (int mt = 0; mt < 2; mt++)
#pragma unroll
        for (int nn = 0; nn < 4; nn++) {
            const int col = n0 + wn * 32 + nn * 8 + 2 * tg;
            const float b0 = bias[col], b1 = bias[col + 1];
#pragma unroll
            for (int h = 0; h < 2; h++) {
                const long row = m0 + wm * 32 + mt * 16 + g + 8 * h;
                float vx = acc[mt][nn][2 * h] + b0;
                float vy = acc[mt][nn][2 * h + 1] + b1;
                if (EM == 1) {
                    if (col < 192) { vx *= QSCALE; vy *= QSCALE; }
                }
                if (EM == 2) {
                    float2 rv = *reinterpret_cast<const float2*>(R + row * (long)N + col);
                    vx += rv.x; vy += rv.y;
                }
                if (EM == 4) {
                    vx = 0.5f * vx * (1.0f + erff(vx * 0.70710678118654752f));
                    vy = 0.5f * vy * (1.0f + erff(vy * 0.70710678118654752f));
                    uint32_t hp, lp;
                    split2(vx, vy, hp, lp);
                    const long e = (row * (long)N + col) >> 1;
                    reinterpret_cast<uint32_t*>(Yhi)[e] = hp;
                    reinterpret_cast<uint32_t*>(Ylo)[e] = lp;
                } else {
                    *reinterpret_cast<float2*>(Y + row * (long)N + col) = make_float2(vx, vy);
                }
            }
        }
}

// ---------------- weight preconversion ----------------
__global__ void w_conv_kernel(const float* __restrict__ w, bf16* __restrict__ hi,
                              bf16* __restrict__ lo, int n) {
    int i = blockIdx.x * 256 + threadIdx.x;
    if (i < n) {
        float v = w[i];
        bf16 h = __float2bfloat16(v);
        hi[i] = h;
        lo[i] = __float2bfloat16(v - __bfloat162float(h));
    }
}

// ---------------- LN fused stats+apply -> bf16 hi/lo ----------------
__global__ void ln_apply_kernel(const float* __restrict__ X,
                                const float* __restrict__ gamma, const float* __restrict__ beta,
                                bf16* __restrict__ hi, bf16* __restrict__ lo) {
    int tok = blockIdx.x * 8 + (threadIdx.x >> 5);
    int lane = threadIdx.x & 31;
    const float* p = X + (long)tok * Cv;
    float v[6];
#pragma unroll
    for (int i = 0; i < 6; i++) v[i] = p[lane + i * 32];
    float s = v[0] + v[1] + v[2] + v[3] + v[4] + v[5];
#pragma unroll
    for (int o = 16; o > 0; o >>= 1) s += __shfl_xor_sync(~0u, s, o);
    float mu = s * (1.0f / Cv);
    float qv = 0.f;
#pragma unroll
    for (int i = 0; i < 6; i++) { float d = v[i] - mu; qv += d * d; }
#pragma unroll
    for (int o = 16; o > 0; o >>= 1) qv += __shfl_xor_sync(~0u, qv, o);
    float rs = rsqrtf(qv * (1.0f / Cv) + 1e-5f);
#pragma unroll
    for (int i = 0; i < 6; i++) {
        int c = lane + i * 32;
        float val = (v[i] - mu) * rs * gamma[c] + beta[c];
        bf16 h = __float2bfloat16(val);
        hi[(long)tok * Cv + c] = h;
        lo[(long)tok * Cv + c] = __float2bfloat16(val - __bfloat162float(h));
    }
}

// ---------------- spatial window attention -> bf16 hi/lo ----------------
__global__ void __launch_bounds__(128) attn_spatial_kernel(const float* __restrict__ qkv,
                                                           bf16* __restrict__ ohi,
                                                           bf16* __restrict__ olo) {
    __shared__ float qs[49][33], ks[49][33], vs[49][33];
    __shared__ float sc[49][52];
    const int gh = blockIdx.x;
    const int g = gh / 6, h = gh % 6;
    const int b = g >> 9;
    const int rem = g & 511;
    const int win = rem >> 3, t = rem & 7;
    const int wh = win >> 3, ww = win & 7;
    const int tid = threadIdx.x;
    const long frame = (long)(b * 8 + t) * Lv;

    for (int idx = tid; idx < 49 * 32; idx += 128) {
        int i = idx >> 5, j = idx & 31;
        int l = (wh * 7 + i / 7) * 56 + ww * 7 + (i % 7);
        long base = (frame + l) * 576 + h * 32 + j;
        qs[i][j] = qkv[base];
        ks[i][j] = qkv[base + 192];
        vs[i][j] = qkv[base + 384];
    }
    __syncthreads();

    for (int u = tid; u < 49 * 13; u += 128) {
        int i = u / 13, jb = (u % 13) * 4;
        float a0 = 0.f, a1 = 0.f, a2 = 0.f, a3 = 0.f;
        int j1 = jb + 1 < 49 ? jb + 1 : 48;
        int j2 = jb + 2 < 49 ? jb + 2 : 48;
        int j3 = jb + 3 < 49 ? jb + 3 : 48;
#pragma unroll
        for (int kk = 0; kk < 32; kk++) {
            float qv = qs[i][kk];
            a0 += qv * ks[jb][kk];
            a1 += qv * ks[j1][kk];
            a2 += qv * ks[j2][kk];
            a3 += qv * ks[j3][kk];
        }
        sc[i][jb] = a0;
        if (jb + 1 < 49) sc[i][jb + 1] = a1;
        if (jb + 2 < 49) sc[i][jb + 2] = a2;
        if (jb + 3 < 49) sc[i][jb + 3] = a3;
    }
    __syncthreads();

    if (tid < 49) {
        float mx = -1e30f;
#pragma unroll 7
        for (int j = 0; j < 49; j++) mx = fmaxf(mx, sc[tid][j]);
        float sum = 0.f;
#pragma unroll 7
        for (int j = 0; j < 49; j++) { float e = __expf(sc[tid][j] - mx); sc[tid][j] = e; sum += e; }
        float inv = 1.0f / sum;
#pragma unroll 7
        for (int j = 0; j < 49; j++) sc[tid][j] *= inv;
    }
    __syncthreads();

    for (int u = tid; u < 49 * 8; u += 128) {
        int i = u >> 3, jb = (u & 7) * 4;
        float a0 = 0.f, a1 = 0.f, a2 = 0.f, a3 = 0.f;
#pragma unroll
        for (int n = 0; n < 49; n++) {
            float s = sc[i][n];
            a0 += s * vs[n][jb + 0];
            a1 += s * vs[n][jb + 1];
            a2 += s * vs[n][jb + 2];
            a3 += s * vs[n][jb + 3];
        }
        int l = (wh * 7 + i / 7) * 56 + ww * 7 + (i % 7);
        long e = ((frame + l) * 192 + h * 32 + jb) >> 1;
        uint32_t h01, l01, h23, l23;
        split2(a0, a1, h01, l01);
        split2(a2, a3, h23, l23);
        reinterpret_cast<uint2*>(ohi)[e >> 1] = make_uint2(h01, h23);
        reinterpret_cast<uint2*>(olo)[e >> 1] = make_uint2(l01, l23);
    }
}

// ---------------- temporal attention -> bf16 hi/lo ----------------
__global__ void __launch_bounds__(256) attn_temporal_kernel(const float* __restrict__ qkv,
                                                            bf16* __restrict__ ohi,
                                                            bf16* __restrict__ olo) {
    const int unit = blockIdx.x * 8 + (threadIdx.x >> 5);
    const int lane = threadIdx.x & 31;
    const int g = unit / 6, h = unit % 6;
    const int b = g / Lv, l = g % Lv;
    const long base0 = ((long)(b * 8) * Lv + l) * 576 + h * 32 + lane;
    const long tstride = (long)Lv * 576;

    float q[8], k[8], v[8];
#pragma unroll
    for (int t = 0; t < 8; t++) {
        long base = base0 + (long)t * tstride;
        q[t] = qkv[base];
        k[t] = qkv[base + 192];
        v[t] = qkv[base + 384];
    }
#pragma unroll
    for (int t1 = 0; t1 < 8; t1++) {
        float s[8];
#pragma unroll
        for (int t2 = 0; t2 < 8; t2++) s[t2] = q[t1] * k[t2];
#pragma unroll
        for (int o = 16; o > 0; o >>= 1) {
#pragma unroll
            for (int t2 = 0; t2 < 8; t2++) s[t2] += __shfl_xor_sync(~0u, s[t2], o);
        }
        float mx = s[0];
#pragma unroll
        for (int t2 = 1; t2 < 8; t2++) mx = fmaxf(mx, s[t2]);
        float sum = 0.f;
#pragma unroll
        for (int t2 = 0; t2 < 8; t2++) { s[t2] = __expf(s[t2] - mx); sum += s[t2]; }
        float inv = 1.0f / sum;
        float o = 0.f;
#pragma unroll
        for (int t2 = 0; t2 < 8; t2++) o += s[t2] * v[t2];
        o *= inv;
        long e = ((long)(b * 8 + t1) * Lv + l) * 192 + h * 32 + lane;
        bf16 hb = __float2bfloat16(o);
        ohi[e] = hb;
        olo[e] = __float2bfloat16(o - __bfloat162float(hb));
    }
}

// ---------------- launcher ----------------
extern "C" void kernel_launch(void* const* d_in, const int* in_sizes, int n_in,
                              void* d_out, int out_size) {
    (void)in_sizes; (void)n_in;
    const float* x        = (const float*)d_in[0];
    const float* norm1_g  = (const float*)d_in[2];
    const float* norm1_b  = (const float*)d_in[3];
    const float* qkv_w    = (const float*)d_in[4];
    const float* qkv_b    = (const float*)d_in[5];
    const float* proj_sp_w = (const float*)d_in[6];
    const float* proj_sp_b = (const float*)d_in[7];
    const float* proj_t_w = (const float*)d_in[8];
    const float* proj_t_b = (const float*)d_in[9];
    const float* norm2_g  = (const float*)d_in[10];
    const float* norm2_b  = (const float*)d_in[11];
    const float* te_fc1_w = (const float*)d_in[12];
    const float* te_fc1_b = (const float*)d_in[13];
    const float* te_fc2_w = (const float*)d_in[14];
    const float* te_fc2_b = (const float*)d_in[15];
    const float* sp_fc1_w = (const float*)d_in[16];
    const float* sp_fc1_b = (const float*)d_in[17];
    const float* sp_fc2_w = (const float*)d_in[18];
    const float* sp_fc2_b = (const float*)d_in[19];
    const float* fuse_w   = (const float*)d_in[20];
    const float* fuse_b   = (const float*)d_in[21];

    float* out = (float*)d_out;
    float *xt, *xsp;
    if ((long)out_size >= 3 * MCl) {
        xt = out + MCl;
        xsp = out + 2 * MCl;
    } else {
        void* p;
        cudaGetSymbolAddress(&p, g_xt_fb);  xt = (float*)p;
        cudaGetSymbolAddress(&p, g_xsp_fb); xsp = (float*)p;
    }
    void* p;
    cudaGetSymbolAddress(&p, g_qkv);    float* qkv = (float*)p;
    cudaGetSymbolAddress(&p, g_a_hi);   bf16* a_hi = (bf16*)p;
    cudaGetSymbolAddress(&p, g_a_lo);   bf16* a_lo = (bf16*)p;
    cudaGetSymbolAddress(&p, g_osp_hi); bf16* osp_hi = (bf16*)p;
    cudaGetSymbolAddress(&p, g_osp_lo); bf16* osp_lo = (bf16*)p;
    cudaGetSymbolAddress(&p, g_ot_hi);  bf16* ot_hi = (bf16*)p;
    cudaGetSymbolAddress(&p, g_ot_lo);  bf16* ot_lo = (bf16*)p;
    cudaGetSymbolAddress(&p, g_h_hi);   bf16* h_hi = (bf16*)p;
    cudaGetSymbolAddress(&p, g_h_lo);   bf16* h_lo = (bf16*)p;
    cudaGetSymbolAddress(&p, g_whi);    bf16* whi = (bf16*)p;
    cudaGetSymbolAddress(&p, g_wlo);    bf16* wlo = (bf16*)p;

    cudaFuncSetAttribute(mma_gemm<192, 0, 1>, cudaFuncAttributeMaxDynamicSharedMemorySize, DSMEM);
    cudaFuncSetAttribute(mma_gemm<192, 0, 2>, cudaFuncAttributeMaxDynamicSharedMemorySize, DSMEM);
    cudaFuncSetAttribute(mma_gemm<192, 0, 4>, cudaFuncAttributeMaxDynamicSharedMemorySize, DSMEM);
    cudaFuncSetAttribute(mma_gemm<768, 0, 2>, cudaFuncAttributeMaxDynamicSharedMemorySize, DSMEM);
    cudaFuncSetAttribute(mma_gemm<384, 2, 0>, cudaFuncAttributeMaxDynamicSharedMemorySize, DSMEM);

    const int MT = Mv / 128;  // 1568; grid x = row tile (fast) — measured-best order

    // 0) weight preconversion (tiny)
    w_conv_kernel<<<(110592 + 255) / 256, 256>>>(qkv_w, whi + WO_QKV, wlo + WO_QKV, 110592);
    w_conv_kernel<<<(36864 + 255) / 256, 256>>>(proj_sp_w, whi + WO_PSP, wlo + WO_PSP, 36864);
    w_conv_kernel<<<(36864 + 255) / 256, 256>>>(proj_t_w, whi + WO_PT, wlo + WO_PT, 36864);
    w_conv_kernel<<<(147456 + 255) / 256, 256>>>(te_fc1_w, whi + WO_TF1, wlo + WO_TF1, 147456);
    w_conv_kernel<<<(147456 + 255) / 256, 256>>>(te_fc2_w, whi + WO_TF2, wlo + WO_TF2, 147456);
    w_conv_kernel<<<(147456 + 255) / 256, 256>>>(sp_fc1_w, whi + WO_SF1, wlo + WO_SF1, 147456);
    w_conv_kernel<<<(147456 + 255) / 256, 256>>>(sp_fc2_w, whi + WO_SF2, wlo + WO_SF2, 147456);
    w_conv_kernel<<<(73728 + 255) / 256, 256>>>(fuse_w, whi + WO_FUSE, wlo + WO_FUSE, 73728);

    // 1) LN1 apply -> a pair
    ln_apply_kernel<<<Mv / 8, 256>>>(x, norm1_g, norm1_b, a_hi, a_lo);
    // 2) QKV = a @ qkv_w^T + b (q pre-scaled)
    mma_gemm<192, 0, 1><<<dim3(MT, 9), 256, DSMEM>>>(
        a_hi, a_lo, nullptr, nullptr, whi + WO_QKV, wlo + WO_QKV, qkv_b, nullptr,
        qkv, nullptr, nullptr, 576);
    // 3) attention
    attn_spatial_kernel<<<4096 * 6, 128>>>(qkv, osp_hi, osp_lo);
    attn_temporal_kernel<<<(Bv * Lv * 6) / 8, 256>>>(qkv, ot_hi, ot_lo);
    // 4) x_sp = osp @ proj_sp^T + b + x ; x_t = ot @ proj_t^T + b + x
    mma_gemm<192, 0, 2><<<dim3(MT, 3), 256, DSMEM>>>(
        osp_hi, osp_lo, nullptr, nullptr, whi + WO_PSP, wlo + WO_PSP, proj_sp_b, x,
        xsp, nullptr, nullptr, 192);
    mma_gemm<192, 0, 2><<<dim3(MT, 3), 256, DSMEM>>>(
        ot_hi, ot_lo, nullptr, nullptr, whi + WO_PT, wlo + WO_PT, proj_t_b, x,
        xt, nullptr, nullptr, 192);
    // 5) temporal MLP
    ln_apply_kernel<<<Mv / 8, 256>>>(xt, norm2_g, norm2_b, a_hi, a_lo);
    mma_gemm<192, 0, 4><<<dim3(MT, 12), 256, DSMEM>>>(
        a_hi, a_lo, nullptr, nullptr, whi + WO_TF1, wlo + WO_TF1, te_fc1_b, nullptr,
        nullptr, h_hi, h_lo, HIDv);
    mma_gemm<768, 0, 2><<<dim3(MT, 3), 256, DSMEM>>>(
        h_hi, h_lo, nullptr, nullptr, whi + WO_TF2, wlo + WO_TF2, te_fc2_b, xt,
        xt, nullptr, nullptr, 192);
    // 6) spatial MLP
    ln_apply_kernel<<<Mv / 8, 256>>>(xsp, norm2_g, norm2_b, a_hi, a_lo);
    mma_gemm<192, 0, 4><<<dim3(MT, 12), 256, DSMEM>>>(
        a_hi, a_lo, nullptr, nullptr, whi + WO_SF1, wlo + WO_SF1, sp_fc1_b, nullptr,
        nullptr, h_hi, h_lo, HIDv);
    mma_gemm<768, 0, 2><<<dim3(MT, 3), 256, DSMEM>>>(
        h_hi, h_lo, nullptr, nullptr, whi + WO_SF2, wlo + WO_SF2, sp_fc2_b, xsp,
        xsp, nullptr, nullptr, 192);
    // 7) out = [xt | xsp] @ fuse_w^T + fuse_b
    mma_gemm<384, 2, 0><<<dim3(MT, 3), 256, DSMEM>>>(
        nullptr, nullptr, xt, xsp, whi + WO_FUSE, wlo + WO_FUSE, fuse_b, nullptr,
        out, nullptr, nullptr, 192);
}

// round 6
// speedup vs baseline: 1.0945x; 1.0945x over previous
#include <cuda_runtime.h>
#include <cuda_bf16.h>
#include <math.h>
#include <stdint.h>

// ---------------- problem constants ----------------
constexpr int Bv = 8, Tv = 8, Hv = 56, Wv = 56, Cv = 192;
constexpr int NHv = 6, Lv = Hv * Wv;                // 3136
constexpr int HIDv = 4 * Cv;                        // 768
constexpr int Mv = Bv * Tv * Lv;                    // 200704 tokens
constexpr long MCl = (long)Mv * Cv;
constexpr float QSCALE = 0.17677669529663687f;      // 32^-0.5

// ---------------- device scratch ----------------
typedef __nv_bfloat16 bf16;
__device__ float g_qkv[(long)Mv * 576];
__device__ bf16 g_a_hi[MCl],  g_a_lo[MCl];
__device__ bf16 g_osp_hi[MCl], g_osp_lo[MCl];
__device__ bf16 g_ot_hi[MCl],  g_ot_lo[MCl];
__device__ bf16 g_h_hi[(long)Mv * HIDv], g_h_lo[(long)Mv * HIDv];
__device__ bf16 g_whi[847872], g_wlo[847872];
__device__ float g_xt_fb[MCl];
__device__ float g_xsp_fb[MCl];

// weight offsets
constexpr int WO_QKV = 0;            // 576x192
constexpr int WO_PSP = 110592;       // 192x192
constexpr int WO_PT  = 147456;       // 192x192
constexpr int WO_TF1 = 184320;       // 768x192
constexpr int WO_TF2 = 331776;       // 192x768
constexpr int WO_SF1 = 479232;       // 768x192
constexpr int WO_SF2 = 626688;       // 192x768
constexpr int WO_FUSE = 774144;      // 192x384

// ---------------- helpers ----------------
__device__ __forceinline__ uint32_t smem_u32(const void* p) {
    uint32_t a;
    asm("{ .reg .u64 t; cvta.to.shared.u64 t, %1; cvt.u32.u64 %0, t; }" : "=r"(a) : "l"(p));
    return a;
}

#define LDSM4(r, addr)                                                        \
    asm volatile("ldmatrix.sync.aligned.m8n8.x4.shared.b16 {%0,%1,%2,%3}, [%4];" \
        : "=r"((r)[0]), "=r"((r)[1]), "=r"((r)[2]), "=r"((r)[3]) : "r"(addr))

#define MMA_BF16(c, a, b0, b1)                                                \
    asm volatile("mma.sync.aligned.m16n8k16.row.col.f32.bf16.bf16.f32 "       \
        "{%0,%1,%2,%3},{%4,%5,%6,%7},{%8,%9},{%0,%1,%2,%3};"                  \
        : "+f"((c)[0]), "+f"((c)[1]), "+f"((c)[2]), "+f"((c)[3])              \
        : "r"((a)[0]), "r"((a)[1]), "r"((a)[2]), "r"((a)[3]), "r"(b0), "r"(b1))

__device__ __forceinline__ void split2(float x, float y, uint32_t& hp, uint32_t& lp) {
    asm("cvt.rn.bf16x2.f32 %0, %1, %2;" : "=r"(hp) : "f"(y), "f"(x));
    float rx = x - __uint_as_float(hp << 16);
    float ry = y - __uint_as_float(hp & 0xFFFF0000u);
    asm("cvt.rn.bf16x2.f32 %0, %1, %2;" : "=r"(lp) : "f"(ry), "f"(rx));
}

__device__ __forceinline__ void cvst80(char* hi, char* lo, int row, int colf, float4 v) {
    uint32_t off = row * 80 + colf * 2;
    uint32_t h01, l01, h23, l23;
    split2(v.x, v.y, h01, l01);
    split2(v.z, v.w, h23, l23);
    *reinterpret_cast<uint2*>(hi + off) = make_uint2(h01, h23);
    *reinterpret_cast<uint2*>(lo + off) = make_uint2(l01, l23);
}

// ---------------- mma.sync fused GEMM, CTA tile 128x96 ----------------
// smem stage (80B rows): Ahi 0 | Alo 10240 | Bhi 20480 | Blo 28160; stage 35840
// AM: 0 preconverted bf16 A; 2 fp32 concat [Af|Af2] converted in loader
// EM: 0 bias; 1 +qscale(cols<192); 2 +residual; 4 +GELU -> dual bf16 out
constexpr int STAGE = 35840;
constexpr int DSMEM = 2 * STAGE;

template <int KD, int AM, int EM>
__global__ void __launch_bounds__(256, 2)
mma_gemm(const bf16* __restrict__ Ahi, const bf16* __restrict__ Alo,
         const float* __restrict__ Af, const float* __restrict__ Af2,
         const bf16* __restrict__ Whi, const bf16* __restrict__ Wlo,
         const float* __restrict__ bias, const float* __restrict__ R,
         float* __restrict__ Y, bf16* __restrict__ Yhi, bf16* __restrict__ Ylo,
         int N) {
    extern __shared__ char sm[];
    const int tid = threadIdx.x;
    const long m0 = (long)blockIdx.x * 128;
    const int n0 = blockIdx.y * 96;
    constexpr int NS = KD / 32;

    // loader mapping: A 2 thr/row (128 rows), B 2 thr/row for tid<192 (96 rows)
    const int ar = tid >> 1, ah = (tid & 1) * 16;
    const int br = tid >> 1, bh = (tid & 1) * 16;   // valid if tid<192
    const bool bact = tid < 192;

    uint4 rah[2], ral[2], rbh[2], rbl[2];
    float4 pa[4];

    auto gload = [&](int s) {
        const int kg = s * 32;
        if (AM == 0) {
            const bf16* pah = Ahi + (m0 + ar) * (long)KD + kg + ah;
            const bf16* pal = Alo + (m0 + ar) * (long)KD + kg + ah;
            rah[0] = *reinterpret_cast<const uint4*>(pah);
            rah[1] = *reinterpret_cast<const uint4*>(pah + 8);
            ral[0] = *reinterpret_cast<const uint4*>(pal);
            ral[1] = *reinterpret_cast<const uint4*>(pal + 8);
        } else {
#pragma unroll
            for (int j = 0; j < 4; j++) {
                int col = kg + ah + j * 4;
                const float* src = (col < 192) ? Af + (m0 + ar) * 192 + col
                                               : Af2 + (m0 + ar) * 192 + (col - 192);
                pa[j] = *reinterpret_cast<const float4*>(src);
            }
        }
        if (bact) {
            const bf16* pwh = Whi + (long)(n0 + br) * KD + kg + bh;
            const bf16* pwl = Wlo + (long)(n0 + br) * KD + kg + bh;
            rbh[0] = *reinterpret_cast<const uint4*>(pwh);
            rbh[1] = *reinterpret_cast<const uint4*>(pwh + 8);
            rbl[0] = *reinterpret_cast<const uint4*>(pwl);
            rbl[1] = *reinterpret_cast<const uint4*>(pwl + 8);
        }
    };
    auto sstore = [&](int buf) {
        char* base = sm + buf * STAGE;
        if (AM == 0) {
            *reinterpret_cast<uint4*>(base + ar * 80 + ah * 2) = rah[0];
            *reinterpret_cast<uint4*>(base + ar * 80 + ah * 2 + 16) = rah[1];
            *reinterpret_cast<uint4*>(base + 10240 + ar * 80 + ah * 2) = ral[0];
            *reinterpret_cast<uint4*>(base + 10240 + ar * 80 + ah * 2 + 16) = ral[1];
        } else {
#pragma unroll
            for (int j = 0; j < 4; j++)
                cvst80(base, base + 10240, ar, ah + j * 4, pa[j]);
        }
        if (bact) {
            *reinterpret_cast<uint4*>(base + 20480 + br * 80 + bh * 2) = rbh[0];
            *reinterpret_cast<uint4*>(base + 20480 + br * 80 + bh * 2 + 16) = rbh[1];
            *reinterpret_cast<uint4*>(base + 28160 + br * 80 + bh * 2) = rbl[0];
            *reinterpret_cast<uint4*>(base + 28160 + br * 80 + bh * 2 + 16) = rbl[1];
        }
    };

    // mma mapping: 8 warps = 4(M) x 2(N); warp tile 32x48
    const int l = tid & 31, wid = tid >> 5;
    const int wm = wid & 3, wn = wid >> 2;
    const int arow = wm * 32 + (l & 15);
    const int acol8 = (l >> 4) * 8;
    const int brow = wn * 48 + (l & 7) + ((l >> 4) << 3);
    const int bcol8 = ((l >> 3) & 1) * 8;
    const uint32_t smb = smem_u32(sm);

    float acc[2][6][4];
#pragma unroll
    for (int i = 0; i < 2; i++)
#pragma unroll
        for (int j = 0; j < 6; j++)
#pragma unroll
            for (int k = 0; k < 4; k++) acc[i][j][k] = 0.f;

    auto mmastage = [&](int buf) {
        const uint32_t base = smb + buf * STAGE;
#pragma unroll
        for (int kt = 0; kt < 2; kt++) {
            uint32_t af[2][4], alr[2][4];
#pragma unroll
            for (int mt = 0; mt < 2; mt++) {
                uint32_t addr = base + (arow + mt * 16) * 80 + (kt * 16 + acol8) * 2;
                LDSM4(af[mt], addr);
                LDSM4(alr[mt], addr + 10240);
            }
#pragma unroll
            for (int nt = 0; nt < 3; nt++) {
                uint32_t bhf[4], blf[4];
                uint32_t addr = base + 20480 + (brow + nt * 16) * 80 + (kt * 16 + bcol8) * 2;
                LDSM4(bhf, addr);
                LDSM4(blf, addr + 7680);
#pragma unroll
                for (int mt = 0; mt < 2; mt++)
#pragma unroll
                    for (int jj = 0; jj < 2; jj++) {
                        const int nn = nt * 2 + jj;
                        MMA_BF16(acc[mt][nn], af[mt], bhf[2 * jj], bhf[2 * jj + 1]);
                        MMA_BF16(acc[mt][nn], af[mt], blf[2 * jj], blf[2 * jj + 1]);
                        MMA_BF16(acc[mt][nn], alr[mt], bhf[2 * jj], bhf[2 * jj + 1]);
                    }
            }
        }
    };

    gload(0); sstore(0);
    gload(1);
    __syncthreads();
    for (int s = 0; s < NS; s++) {
        mmastage(s & 1);
        __syncthreads();
        if (s + 1 < NS) {
            sstore((s + 1) & 1);
            if (s + 2 < NS) gload(s + 2);
            __syncthreads();
        }
    }

    // register epilogue
    const int g = l >> 2, tg = l & 3;
#pragma unroll
    for (int mt = 0; mt < 2; mt++)
#pragma unroll
        for (int nn = 0; nn < 6; nn++) {
            const int col = n0 + wn * 48 + nn * 8 + 2 * tg;
            const float b0 = bias[col], b1 = bias[col + 1];
#pragma unroll
            for (int h = 0; h < 2; h++) {
                const long row = m0 + wm * 32 + mt * 16 + g + 8 * h;
                float vx = acc[mt][nn][2 * h] + b0;
                float vy = acc[mt][nn][2 * h + 1] + b1;
                if (EM == 1) {
                    if (col < 192) { vx *= QSCALE; vy *= QSCALE; }
                }
                if (EM == 2) {
                    float2 rv = *reinterpret_cast<const float2*>(R + row * (long)N + col);
                    vx += rv.x; vy += rv.y;
                }
                if (EM == 4) {
                    vx = 0.5f * vx * (1.0f + erff(vx * 0.70710678118654752f));
                    vy = 0.5f * vy * (1.0f + erff(vy * 0.70710678118654752f));
                    uint32_t hp, lp;
                    split2(vx, vy, hp, lp);
                    const long e = (row * (long)N + col) >> 1;
                    reinterpret_cast<uint32_t*>(Yhi)[e] = hp;
                    reinterpret_cast<uint32_t*>(Ylo)[e] = lp;
                } else {
                    *reinterpret_cast<float2*>(Y + row * (long)N + col) = make_float2(vx, vy);
                }
            }
        }
}

// ---------------- combined weight preconversion (one launch) ----------------
__global__ void w_conv_all_kernel(const float* qkv_w, const float* psp_w, const float* pt_w,
                                  const float* tf1_w, const float* tf2_w, const float* sf1_w,
                                  const float* sf2_w, const float* fuse_w,
                                  bf16* __restrict__ hi, bf16* __restrict__ lo) {
    int i = blockIdx.x * 256 + threadIdx.x;
    if (i >= 847872) return;
    float v;
    if (i < WO_PSP)       v = qkv_w[i - WO_QKV];
    else if (i < WO_PT)   v = psp_w[i - WO_PSP];
    else if (i < WO_TF1)  v = pt_w[i - WO_PT];
    else if (i < WO_TF2)  v = tf1_w[i - WO_TF1];
    else if (i < WO_SF1)  v = tf2_w[i - WO_TF2];
    else if (i < WO_SF2)  v = sf1_w[i - WO_SF1];
    else if (i < WO_FUSE) v = sf2_w[i - WO_SF2];
    else                  v = fuse_w[i - WO_FUSE];
    bf16 h = __float2bfloat16(v);
    hi[i] = h;
    lo[i] = __float2bfloat16(v - __bfloat162float(h));
}

// ---------------- LN fused stats+apply -> bf16 hi/lo ----------------
__global__ void ln_apply_kernel(const float* __restrict__ X,
                                const float* __restrict__ gamma, const float* __restrict__ beta,
                                bf16* __restrict__ hi, bf16* __restrict__ lo) {
    int tok = blockIdx.x * 8 + (threadIdx.x >> 5);
    int lane = threadIdx.x & 31;
    const float* p = X + (long)tok * Cv;
    float v[6];
#pragma unroll
    for (int i = 0; i < 6; i++) v[i] = p[lane + i * 32];
    float s = v[0] + v[1] + v[2] + v[3] + v[4] + v[5];
#pragma unroll
    for (int o = 16; o > 0; o >>= 1) s += __shfl_xor_sync(~0u, s, o);
    float mu = s * (1.0f / Cv);
    float qv = 0.f;
#pragma unroll
    for (int i = 0; i < 6; i++) { float d = v[i] - mu; qv += d * d; }
#pragma unroll
    for (int o = 16; o > 0; o >>= 1) qv += __shfl_xor_sync(~0u, qv, o);
    float rs = rsqrtf(qv * (1.0f / Cv) + 1e-5f);
#pragma unroll
    for (int i = 0; i < 6; i++) {
        int c = lane + i * 32;
        float val = (v[i] - mu) * rs * gamma[c] + beta[c];
        bf16 h = __float2bfloat16(val);
        hi[(long)tok * Cv + c] = h;
        lo[(long)tok * Cv + c] = __float2bfloat16(val - __bfloat162float(h));
    }
}

// ---------------- spatial window attention -> bf16 hi/lo ----------------
__global__ void __launch_bounds__(128) attn_spatial_kernel(const float* __restrict__ qkv,
                                                           bf16* __restrict__ ohi,
                                                           bf16* __restrict__ olo) {
    __shared__ float qs[49][33], ks[49][33], vs[49][33];
    __shared__ float sc[49][52];
    const int gh = blockIdx.x;
    const int g = gh / 6, h = gh % 6;
    const int b = g >> 9;
    const int rem = g & 511;
    const int win = rem >> 3, t = rem & 7;
    const int wh = win >> 3, ww = win & 7;
    const int tid = threadIdx.x;
    const long frame = (long)(b * 8 + t) * Lv;

    for (int idx = tid; idx < 49 * 32; idx += 128) {
        int i = idx >> 5, j = idx & 31;
        int l = (wh * 7 + i / 7) * 56 + ww * 7 + (i % 7);
        long base = (frame + l) * 576 + h * 32 + j;
        qs[i][j] = qkv[base];
        ks[i][j] = qkv[base + 192];
        vs[i][j] = qkv[base + 384];
    }
    __syncthreads();

    for (int u = tid; u < 49 * 13; u += 128) {
        int i = u / 13, jb = (u % 13) * 4;
        float a0 = 0.f, a1 = 0.f, a2 = 0.f, a3 = 0.f;
        int j1 = jb + 1 < 49 ? jb + 1 : 48;
        int j2 = jb + 2 < 49 ? jb + 2 : 48;
        int j3 = jb + 3 < 49 ? jb + 3 : 48;
#pragma unroll
        for (int kk = 0; kk < 32; kk++) {
            float qv = qs[i][kk];
            a0 += qv * ks[jb][kk];
            a1 += qv * ks[j1][kk];
            a2 += qv * ks[j2][kk];
            a3 += qv * ks[j3][kk];
        }
        sc[i][jb] = a0;
        if (jb + 1 < 49) sc[i][jb + 1] = a1;
        if (jb + 2 < 49) sc[i][jb + 2] = a2;
        if (jb + 3 < 49) sc[i][jb + 3] = a3;
    }
    __syncthreads();

    if (tid < 49) {
        float mx = -1e30f;
#pragma unroll 7
        for (int j = 0; j < 49; j++) mx = fmaxf(mx, sc[tid][j]);
        float sum = 0.f;
#pragma unroll 7
        for (int j = 0; j < 49; j++) { float e = __expf(sc[tid][j] - mx); sc[tid][j] = e; sum += e; }
        float inv = 1.0f / sum;
#pragma unroll 7
        for (int j = 0; j < 49; j++) sc[tid][j] *= inv;
    }
    __syncthreads();

    for (int u = tid; u < 49 * 8; u += 128) {
        int i = u >> 3, jb = (u & 7) * 4;
        float a0 = 0.f, a1 = 0.f, a2 = 0.f, a3 = 0.f;
#pragma unroll
        for (int n = 0; n < 49; n++) {
            float s = sc[i][n];
            a0 += s * vs[n][jb + 0];
            a1 += s * vs[n][jb + 1];
            a2 += s * vs[n][jb + 2];
            a3 += s * vs[n][jb + 3];
        }
        int l = (wh * 7 + i / 7) * 56 + ww * 7 + (i % 7);
        long e = ((frame + l) * 192 + h * 32 + jb) >> 1;
        uint32_t h01, l01, h23, l23;
        split2(a0, a1, h01, l01);
        split2(a2, a3, h23, l23);
        reinterpret_cast<uint2*>(ohi)[e >> 1] = make_uint2(h01, h23);
        reinterpret_cast<uint2*>(olo)[e >> 1] = make_uint2(l01, l23);
    }
}

// ---------------- temporal attention -> bf16 hi/lo ----------------
__global__ void __launch_bounds__(256) attn_temporal_kernel(const float* __restrict__ qkv,
                                                            bf16* __restrict__ ohi,
                                                            bf16* __restrict__ olo) {
    const int unit = blockIdx.x * 8 + (threadIdx.x >> 5);
    const int lane = threadIdx.x & 31;
    const int g = unit / 6, h = unit % 6;
    const int b = g / Lv, l = g % Lv;
    const long base0 = ((long)(b * 8) * Lv + l) * 576 + h * 32 + lane;
    const long tstride = (long)Lv * 576;

    float q[8], k[8], v[8];
#pragma unroll
    for (int t = 0; t < 8; t++) {
        long base = base0 + (long)t * tstride;
        q[t] = qkv[base];
        k[t] = qkv[base + 192];
        v[t] = qkv[base + 384];
    }
#pragma unroll
    for (int t1 = 0; t1 < 8; t1++) {
        float s[8];
#pragma unroll
        for (int t2 = 0; t2 < 8; t2++) s[t2] = q[t1] * k[t2];
#pragma unroll
        for (int o = 16; o > 0; o >>= 1) {
#pragma unroll
            for (int t2 = 0; t2 < 8; t2++) s[t2] += __shfl_xor_sync(~0u, s[t2], o);
        }
        float mx = s[0];
#pragma unroll
        for (int t2 = 1; t2 < 8; t2++) mx = fmaxf(mx, s[t2]);
        float sum = 0.f;
#pragma unroll
        for (int t2 = 0; t2 < 8; t2++) { s[t2] = __expf(s[t2] - mx); sum += s[t2]; }
        float inv = 1.0f / sum;
        float o = 0.f;
#pragma unroll
        for (int t2 = 0; t2 < 8; t2++) o += s[t2] * v[t2];
        o *= inv;
        long e = ((long)(b * 8 + t1) * Lv + l) * 192 + h * 32 + lane;
        bf16 hb = __float2bfloat16(o);
        ohi[e] = hb;
        olo[e] = __float2bfloat16(o - __bfloat162float(hb));
    }
}

// ---------------- launcher ----------------
extern "C" void kernel_launch(void* const* d_in, const int* in_sizes, int n_in,
                              void* d_out, int out_size) {
    (void)in_sizes; (void)n_in;
    const float* x        = (const float*)d_in[0];
    const float* norm1_g  = (const float*)d_in[2];
    const float* norm1_b  = (const float*)d_in[3];
    const float* qkv_w    = (const float*)d_in[4];
    const float* qkv_b    = (const float*)d_in[5];
    const float* proj_sp_w = (const float*)d_in[6];
    const float* proj_sp_b = (const float*)d_in[7];
    const float* proj_t_w = (const float*)d_in[8];
    const float* proj_t_b = (const float*)d_in[9];
    const float* norm2_g  = (const float*)d_in[10];
    const float* norm2_b  = (const float*)d_in[11];
    const float* te_fc1_w = (const float*)d_in[12];
    const float* te_fc1_b = (const float*)d_in[13];
    const float* te_fc2_w = (const float*)d_in[14];
    const float* te_fc2_b = (const float*)d_in[15];
    const float* sp_fc1_w = (const float*)d_in[16];
    const float* sp_fc1_b = (const float*)d_in[17];
    const float* sp_fc2_w = (const float*)d_in[18];
    const float* sp_fc2_b = (const float*)d_in[19];
    const float* fuse_w   = (const float*)d_in[20];
    const float* fuse_b   = (const float*)d_in[21];

    float* out = (float*)d_out;
    float *xt, *xsp;
    if ((long)out_size >= 3 * MCl) {
        xt = out + MCl;
        xsp = out + 2 * MCl;
    } else {
        void* p;
        cudaGetSymbolAddress(&p, g_xt_fb);  xt = (float*)p;
        cudaGetSymbolAddress(&p, g_xsp_fb); xsp = (float*)p;
    }
    void* p;
    cudaGetSymbolAddress(&p, g_qkv);    float* qkv = (float*)p;
    cudaGetSymbolAddress(&p, g_a_hi);   bf16* a_hi = (bf16*)p;
    cudaGetSymbolAddress(&p, g_a_lo);   bf16* a_lo = (bf16*)p;
    cudaGetSymbolAddress(&p, g_osp_hi); bf16* osp_hi = (bf16*)p;
    cudaGetSymbolAddress(&p, g_osp_lo); bf16* osp_lo = (bf16*)p;
    cudaGetSymbolAddress(&p, g_ot_hi);  bf16* ot_hi = (bf16*)p;
    cudaGetSymbolAddress(&p, g_ot_lo);  bf16* ot_lo = (bf16*)p;
    cudaGetSymbolAddress(&p, g_h_hi);   bf16* h_hi = (bf16*)p;
    cudaGetSymbolAddress(&p, g_h_lo);   bf16* h_lo = (bf16*)p;
    cudaGetSymbolAddress(&p, g_whi);    bf16* whi = (bf16*)p;
    cudaGetSymbolAddress(&p, g_wlo);    bf16* wlo = (bf16*)p;

    cudaFuncSetAttribute(mma_gemm<192, 0, 1>, cudaFuncAttributeMaxDynamicSharedMemorySize, DSMEM);
    cudaFuncSetAttribute(mma_gemm<192, 0, 2>, cudaFuncAttributeMaxDynamicSharedMemorySize, DSMEM);
    cudaFuncSetAttribute(mma_gemm<192, 0, 4>, cudaFuncAttributeMaxDynamicSharedMemorySize, DSMEM);
    cudaFuncSetAttribute(mma_gemm<768, 0, 2>, cudaFuncAttributeMaxDynamicSharedMemorySize, DSMEM);
    cudaFuncSetAttribute(mma_gemm<384, 2, 0>, cudaFuncAttributeMaxDynamicSharedMemorySize, DSMEM);

    const int MT = Mv / 128;  // 1568

    // launch 0: weight preconversion (single kernel)
    w_conv_all_kernel<<<(847872 + 255) / 256, 256>>>(
        qkv_w, proj_sp_w, proj_t_w, te_fc1_w, te_fc2_w, sp_fc1_w, sp_fc2_w, fuse_w, whi, wlo);
    // launch 1: LN1 apply
    ln_apply_kernel<<<Mv / 8, 256>>>(x, norm1_g, norm1_b, a_hi, a_lo);
    // launch 2: QKV (N=576 -> 6 col tiles)
    mma_gemm<192, 0, 1><<<dim3(MT, 6), 256, DSMEM>>>(
        a_hi, a_lo, nullptr, nullptr, whi + WO_QKV, wlo + WO_QKV, qkv_b, nullptr,
        qkv, nullptr, nullptr, 576);
    // launch 3-4: attention
    attn_spatial_kernel<<<4096 * 6, 128>>>(qkv, osp_hi, osp_lo);
    attn_temporal_kernel<<<(Bv * Lv * 6) / 8, 256>>>(qkv, ot_hi, ot_lo);
    // launch 5 (ncu capture target): x_sp = osp @ proj_sp^T + b + x
    mma_gemm<192, 0, 2><<<dim3(MT, 2), 256, DSMEM>>>(
        osp_hi, osp_lo, nullptr, nullptr, whi + WO_PSP, wlo + WO_PSP, proj_sp_b, x,
        xsp, nullptr, nullptr, 192);
    // x_t = ot @ proj_t^T + b + x
    mma_gemm<192, 0, 2><<<dim3(MT, 2), 256, DSMEM>>>(
        ot_hi, ot_lo, nullptr, nullptr, whi + WO_PT, wlo + WO_PT, proj_t_b, x,
        xt, nullptr, nullptr, 192);
    // temporal MLP
    ln_apply_kernel<<<Mv / 8, 256>>>(xt, norm2_g, norm2_b, a_hi, a_lo);
    mma_gemm<192, 0, 4><<<dim3(MT, 8), 256, DSMEM>>>(
        a_hi, a_lo, nullptr, nullptr, whi + WO_TF1, wlo + WO_TF1, te_fc1_b, nullptr,
        nullptr, h_hi, h_lo, HIDv);
    mma_gemm<768, 0, 2><<<dim3(MT, 2), 256, DSMEM>>>(
        h_hi, h_lo, nullptr, nullptr, whi + WO_TF2, wlo + WO_TF2, te_fc2_b, xt,
        xt, nullptr, nullptr, 192);
    // spatial MLP
    ln_apply_kernel<<<Mv / 8, 256>>>(xsp, norm2_g, norm2_b, a_hi, a_lo);
    mma_gemm<192, 0, 4><<<dim3(MT, 8), 256, DSMEM>>>(
        a_hi, a_lo, nullptr, nullptr, whi + WO_SF1, wlo + WO_SF1, sp_fc1_b, nullptr,
        nullptr, h_hi, h_lo, HIDv);
    mma_gemm<768, 0, 2><<<dim3(MT, 2), 256, DSMEM>>>(
        h_hi, h_lo, nullptr, nullptr, whi + WO_SF2, wlo + WO_SF2, sp_fc2_b, xsp,
        xsp, nullptr, nullptr, 192);
    // fuse
    mma_gemm<384, 2, 0><<<dim3(MT, 2), 256, DSMEM>>>(
        nullptr, nullptr, xt, xsp, whi + WO_FUSE, wlo + WO_FUSE, fuse_b, nullptr,
        out, nullptr, nullptr, 192);
}

// round 7
// speedup vs baseline: 1.1539x; 1.0543x over previous
#include <cuda_runtime.h>
#include <cuda_bf16.h>
#include <math.h>
#include <stdint.h>

// ---------------- problem constants ----------------
constexpr int Bv = 8, Tv = 8, Hv = 56, Wv = 56, Cv = 192;
constexpr int NHv = 6, Lv = Hv * Wv;                // 3136
constexpr int HIDv = 4 * Cv;                        // 768
constexpr int Mv = Bv * Tv * Lv;                    // 200704 tokens
constexpr long MCl = (long)Mv * Cv;
constexpr float QSCALE = 0.17677669529663687f;      // 32^-0.5

// ---------------- device scratch ----------------
typedef __nv_bfloat16 bf16;
__device__ float g_qkv[(long)Mv * 576];
__device__ bf16 g_a_hi[MCl],  g_a_lo[MCl];
__device__ bf16 g_osp_hi[MCl], g_osp_lo[MCl];
__device__ bf16 g_ot_hi[MCl],  g_ot_lo[MCl];
__device__ bf16 g_h_hi[(long)Mv * HIDv], g_h_lo[(long)Mv * HIDv];
__device__ bf16 g_cat_hi[(long)Mv * 384], g_cat_lo[(long)Mv * 384];
__device__ bf16 g_whi[847872], g_wlo[847872];
__device__ float g_xt_fb[MCl];
__device__ float g_xsp_fb[MCl];

// weight offsets
constexpr int WO_QKV = 0;            // 576x192
constexpr int WO_PSP = 110592;       // 192x192
constexpr int WO_PT  = 147456;       // 192x192
constexpr int WO_TF1 = 184320;       // 768x192
constexpr int WO_TF2 = 331776;       // 192x768
constexpr int WO_SF1 = 479232;       // 768x192
constexpr int WO_SF2 = 626688;       // 192x768
constexpr int WO_FUSE = 774144;      // 192x384

// ---------------- helpers ----------------
__device__ __forceinline__ uint32_t smem_u32(const void* p) {
    uint32_t a;
    asm("{ .reg .u64 t; cvta.to.shared.u64 t, %1; cvt.u32.u64 %0, t; }" : "=r"(a) : "l"(p));
    return a;
}

#define LDSM4(r, addr)                                                        \
    asm volatile("ldmatrix.sync.aligned.m8n8.x4.shared.b16 {%0,%1,%2,%3}, [%4];" \
        : "=r"((r)[0]), "=r"((r)[1]), "=r"((r)[2]), "=r"((r)[3]) : "r"(addr))

#define MMA_BF16(c, a, b0, b1)                                                \
    asm volatile("mma.sync.aligned.m16n8k16.row.col.f32.bf16.bf16.f32 "       \
        "{%0,%1,%2,%3},{%4,%5,%6,%7},{%8,%9},{%0,%1,%2,%3};"                  \
        : "+f"((c)[0]), "+f"((c)[1]), "+f"((c)[2]), "+f"((c)[3])              \
        : "r"((a)[0]), "r"((a)[1]), "r"((a)[2]), "r"((a)[3]), "r"(b0), "r"(b1))

#define CP16(smem, gptr)                                                      \
    asm volatile("cp.async.cg.shared.global [%0], [%1], 16;"                  \
        :: "r"(smem), "l"(gptr) : "memory")
#define CP_COMMIT() asm volatile("cp.async.commit_group;" ::: "memory")
#define CP_WAIT1()  asm volatile("cp.async.wait_group 1;" ::: "memory")

__device__ __forceinline__ void split2(float x, float y, uint32_t& hp, uint32_t& lp) {
    asm("cvt.rn.bf16x2.f32 %0, %1, %2;" : "=r"(hp) : "f"(y), "f"(x));
    float rx = x - __uint_as_float(hp << 16);
    float ry = y - __uint_as_float(hp & 0xFFFF0000u);
    asm("cvt.rn.bf16x2.f32 %0, %1, %2;" : "=r"(lp) : "f"(ry), "f"(rx));
}

// ---------------- cp.async pipelined GEMM, CTA tile 128x96, 3-stage ring ----------------
// smem stage (80B rows): Ahi 0 | Alo 10240 | Bhi 20480 | Blo 28160; stage 35840
// EM: 0 bias; 1 +qscale(cols<192); 2 +residual (+optional bf16 concat out); 4 +GELU dual bf16
constexpr int STAGE = 35840;
constexpr int NSTG = 3;
constexpr int DSMEM = NSTG * STAGE;

template <int KD, int EM>
__global__ void __launch_bounds__(256, 2)
mma_gemm(const bf16* __restrict__ Ahi, const bf16* __restrict__ Alo,
         const bf16* __restrict__ Whi, const bf16* __restrict__ Wlo,
         const float* __restrict__ bias, const float* __restrict__ R,
         float* __restrict__ Y, bf16* __restrict__ Yhi, bf16* __restrict__ Ylo,
         bf16* __restrict__ CatHi, bf16* __restrict__ CatLo, int catoff, int N) {
    extern __shared__ char sm[];
    const int tid = threadIdx.x;
    const long m0 = (long)blockIdx.x * 128;
    const int n0 = blockIdx.y * 96;
    constexpr int NS = KD / 32;
    const uint32_t smb = smem_u32(sm);

    // cp.async mapping: A 2 thr/row (128 rows), B 2 thr/row for tid<192 (96 rows)
    const int ar = tid >> 1, aoff = (tid & 1) * 32;   // byte offset in 64B row chunk
    const int br = tid >> 1, boff = (tid & 1) * 32;
    const bool bact = tid < 192;

    auto fill = [&](int s) {
        const int buf = s % NSTG;
        const uint32_t sb = smb + buf * STAGE;
        {
            const char* g = reinterpret_cast<const char*>(Ahi + (m0 + ar) * (long)KD + s * 32) + aoff;
            uint32_t d = sb + ar * 80 + aoff;
            CP16(d, g); CP16(d + 16, g + 16);
            const char* g2 = reinterpret_cast<const char*>(Alo + (m0 + ar) * (long)KD + s * 32) + aoff;
            uint32_t d2 = sb + 10240 + ar * 80 + aoff;
            CP16(d2, g2); CP16(d2 + 16, g2 + 16);
        }
        if (bact) {
            const char* g = reinterpret_cast<const char*>(Whi + (long)(n0 + br) * KD + s * 32) + boff;
            uint32_t d = sb + 20480 + br * 80 + boff;
            CP16(d, g); CP16(d + 16, g + 16);
            const char* g2 = reinterpret_cast<const char*>(Wlo + (long)(n0 + br) * KD + s * 32) + boff;
            uint32_t d2 = sb + 28160 + br * 80 + boff;
            CP16(d2, g2); CP16(d2 + 16, g2 + 16);
        }
    };

    // mma mapping: 8 warps = 4(M) x 2(N); warp tile 32x48
    const int l = tid & 31, wid = tid >> 5;
    const int wm = wid & 3, wn = wid >> 2;
    const int arow = wm * 32 + (l & 15);
    const int acol8 = (l >> 4) * 8;
    const int brow = wn * 48 + (l & 7) + ((l >> 4) << 3);
    const int bcol8 = ((l >> 3) & 1) * 8;

    float acc[2][6][4];
#pragma unroll
    for (int i = 0; i < 2; i++)
#pragma unroll
        for (int j = 0; j < 6; j++)
#pragma unroll
            for (int k = 0; k < 4; k++) acc[i][j][k] = 0.f;

    auto mmastage = [&](int buf) {
        const uint32_t base = smb + buf * STAGE;
#pragma unroll
        for (int kt = 0; kt < 2; kt++) {
            uint32_t af[2][4], alr[2][4];
#pragma unroll
            for (int mt = 0; mt < 2; mt++) {
                uint32_t addr = base + (arow + mt * 16) * 80 + (kt * 16 + acol8) * 2;
                LDSM4(af[mt], addr);
                LDSM4(alr[mt], addr + 10240);
            }
#pragma unroll
            for (int nt = 0; nt < 3; nt++) {
                uint32_t bhf[4], blf[4];
                uint32_t addr = base + 20480 + (brow + nt * 16) * 80 + (kt * 16 + bcol8) * 2;
                LDSM4(bhf, addr);
                LDSM4(blf, addr + 7680);
#pragma unroll
                for (int mt = 0; mt < 2; mt++)
#pragma unroll
                    for (int jj = 0; jj < 2; jj++) {
                        const int nn = nt * 2 + jj;
                        MMA_BF16(acc[mt][nn], af[mt], bhf[2 * jj], bhf[2 * jj + 1]);
                        MMA_BF16(acc[mt][nn], af[mt], blf[2 * jj], blf[2 * jj + 1]);
                        MMA_BF16(acc[mt][nn], alr[mt], bhf[2 * jj], bhf[2 * jj + 1]);
                    }
            }
        }
    };

    // pipeline: 2 stages in flight, 1 barrier per stage
    fill(0); CP_COMMIT();
    fill(1); CP_COMMIT();
    for (int s = 0; s < NS; s++) {
        CP_WAIT1();
        __syncthreads();
        mmastage(s % NSTG);
        if (s + 2 < NS) fill(s + 2);
        CP_COMMIT();
    }

    // register epilogue
    const int g = l >> 2, tg = l & 3;
#pragma unroll
    for (int mt = 0; mt < 2; mt++)
#pragma unroll
        for (int nn = 0; nn < 6; nn++) {
            const int col = n0 + wn * 48 + nn * 8 + 2 * tg;
            const float b0 = bias[col], b1 = bias[col + 1];
#pragma unroll
            for (int h = 0; h < 2; h++) {
                const long row = m0 + wm * 32 + mt * 16 + g + 8 * h;
                float vx = acc[mt][nn][2 * h] + b0;
                float vy = acc[mt][nn][2 * h + 1] + b1;
                if (EM == 1) {
                    if (col < 192) { vx *= QSCALE; vy *= QSCALE; }
                    *reinterpret_cast<float2*>(Y + row * (long)N + col) = make_float2(vx, vy);
                }
                if (EM == 0) {
                    *reinterpret_cast<float2*>(Y + row * (long)N + col) = make_float2(vx, vy);
                }
                if (EM == 2) {
                    float2 rv = *reinterpret_cast<const float2*>(R + row * (long)N + col);
                    vx += rv.x; vy += rv.y;
                    *reinterpret_cast<float2*>(Y + row * (long)N + col) = make_float2(vx, vy);
                    if (CatHi) {
                        uint32_t hp, lp;
                        split2(vx, vy, hp, lp);
                        const long e = (row * 384 + catoff + col) >> 1;
                        reinterpret_cast<uint32_t*>(CatHi)[e] = hp;
                        reinterpret_cast<uint32_t*>(CatLo)[e] = lp;
                    }
                }
                if (EM == 4) {
                    vx = 0.5f * vx * (1.0f + erff(vx * 0.70710678118654752f));
                    vy = 0.5f * vy * (1.0f + erff(vy * 0.70710678118654752f));
                    uint32_t hp, lp;
                    split2(vx, vy, hp, lp);
                    const long e = (row * (long)N + col) >> 1;
                    reinterpret_cast<uint32_t*>(Yhi)[e] = hp;
                    reinterpret_cast<uint32_t*>(Ylo)[e] = lp;
                }
            }
        }
}

// ---------------- combined weight preconversion ----------------
__global__ void w_conv_all_kernel(const float* qkv_w, const float* psp_w, const float* pt_w,
                                  const float* tf1_w, const float* tf2_w, const float* sf1_w,
                                  const float* sf2_w, const float* fuse_w,
                                  bf16* __restrict__ hi, bf16* __restrict__ lo) {
    int i = blockIdx.x * 256 + threadIdx.x;
    if (i >= 847872) return;
    float v;
    if (i < WO_PSP)       v = qkv_w[i - WO_QKV];
    else if (i < WO_PT)   v = psp_w[i - WO_PSP];
    else if (i < WO_TF1)  v = pt_w[i - WO_PT];
    else if (i < WO_TF2)  v = tf1_w[i - WO_TF1];
    else if (i < WO_SF1)  v = tf2_w[i - WO_TF2];
    else if (i < WO_SF2)  v = sf1_w[i - WO_SF1];
    else if (i < WO_FUSE) v = sf2_w[i - WO_SF2];
    else                  v = fuse_w[i - WO_FUSE];
    bf16 h = __float2bfloat16(v);
    hi[i] = h;
    lo[i] = __float2bfloat16(v - __bfloat162float(h));
}

// ---------------- LN fused stats+apply -> bf16 hi/lo ----------------
__global__ void ln_apply_kernel(const float* __restrict__ X,
                                const float* __restrict__ gamma, const float* __restrict__ beta,
                                bf16* __restrict__ hi, bf16* __restrict__ lo) {
    int tok = blockIdx.x * 8 + (threadIdx.x >> 5);
    int lane = threadIdx.x & 31;
    const float* p = X + (long)tok * Cv;
    float v[6];
#pragma unroll
    for (int i = 0; i < 6; i++) v[i] = p[lane + i * 32];
    float s = v[0] + v[1] + v[2] + v[3] + v[4] + v[5];
#pragma unroll
    for (int o = 16; o > 0; o >>= 1) s += __shfl_xor_sync(~0u, s, o);
    float mu = s * (1.0f / Cv);
    float qv = 0.f;
#pragma unroll
    for (int i = 0; i < 6; i++) { float d = v[i] - mu; qv += d * d; }
#pragma unroll
    for (int o = 16; o > 0; o >>= 1) qv += __shfl_xor_sync(~0u, qv, o);
    float rs = rsqrtf(qv * (1.0f / Cv) + 1e-5f);
#pragma unroll
    for (int i = 0; i < 6; i++) {
        int c = lane + i * 32;
        float val = (v[i] - mu) * rs * gamma[c] + beta[c];
        bf16 h = __float2bfloat16(val);
        hi[(long)tok * Cv + c] = h;
        lo[(long)tok * Cv + c] = __float2bfloat16(val - __bfloat162float(h));
    }
}

// ---------------- spatial window attention -> bf16 hi/lo ----------------
__global__ void __launch_bounds__(128) attn_spatial_kernel(const float* __restrict__ qkv,
                                                           bf16* __restrict__ ohi,
                                                           bf16* __restrict__ olo) {
    __shared__ float qs[49][33], ks[49][33], vs[49][33];
    __shared__ float sc[49][52];
    const int gh = blockIdx.x;
    const int g = gh / 6, h = gh % 6;
    const int b = g >> 9;
    const int rem = g & 511;
    const int win = rem >> 3, t = rem & 7;
    const int wh = win >> 3, ww = win & 7;
    const int tid = threadIdx.x;
    const long frame = (long)(b * 8 + t) * Lv;

    for (int idx = tid; idx < 49 * 32; idx += 128) {
        int i = idx >> 5, j = idx & 31;
        int l = (wh * 7 + i / 7) * 56 + ww * 7 + (i % 7);
        long base = (frame + l) * 576 + h * 32 + j;
        qs[i][j] = qkv[base];
        ks[i][j] = qkv[base + 192];
        vs[i][j] = qkv[base + 384];
    }
    __syncthreads();

    for (int u = tid; u < 49 * 13; u += 128) {
        int i = u / 13, jb = (u % 13) * 4;
        float a0 = 0.f, a1 = 0.f, a2 = 0.f, a3 = 0.f;
        int j1 = jb + 1 < 49 ? jb + 1 : 48;
        int j2 = jb + 2 < 49 ? jb + 2 : 48;
        int j3 = jb + 3 < 49 ? jb + 3 : 48;
#pragma unroll
        for (int kk = 0; kk < 32; kk++) {
            float qv = qs[i][kk];
            a0 += qv * ks[jb][kk];
            a1 += qv * ks[j1][kk];
            a2 += qv * ks[j2][kk];
            a3 += qv * ks[j3][kk];
        }
        sc[i][jb] = a0;
        if (jb + 1 < 49) sc[i][jb + 1] = a1;
        if (jb + 2 < 49) sc[i][jb + 2] = a2;
        if (jb + 3 < 49) sc[i][jb + 3] = a3;
    }
    __syncthreads();

    if (tid < 49) {
        float mx = -1e30f;
#pragma unroll 7
        for (int j = 0; j < 49; j++) mx = fmaxf(mx, sc[tid][j]);
        float sum = 0.f;
#pragma unroll 7
        for (int j = 0; j < 49; j++) { float e = __expf(sc[tid][j] - mx); sc[tid][j] = e; sum += e; }
        float inv = 1.0f / sum;
#pragma unroll 7
        for (int j = 0; j < 49; j++) sc[tid][j] *= inv;
    }
    __syncthreads();

    for (int u = tid; u < 49 * 8; u += 128) {
        int i = u >> 3, jb = (u & 7) * 4;
        float a0 = 0.f, a1 = 0.f, a2 = 0.f, a3 = 0.f;
#pragma unroll
        for (int n = 0; n < 49; n++) {
            float s = sc[i][n];
            a0 += s * vs[n][jb + 0];
            a1 += s * vs[n][jb + 1];
            a2 += s * vs[n][jb + 2];
            a3 += s * vs[n][jb + 3];
        }
        int l = (wh * 7 + i / 7) * 56 + ww * 7 + (i % 7);
        long e = ((frame + l) * 192 + h * 32 + jb) >> 1;
        uint32_t h01, l01, h23, l23;
        split2(a0, a1, h01, l01);
        split2(a2, a3, h23, l23);
        reinterpret_cast<uint2*>(ohi)[e >> 1] = make_uint2(h01, h23);
        reinterpret_cast<uint2*>(olo)[e >> 1] = make_uint2(l01, l23);
    }
}

// ---------------- temporal attention -> bf16 hi/lo ----------------
__global__ void __launch_bounds__(256) attn_temporal_kernel(const float* __restrict__ qkv,
                                                            bf16* __restrict__ ohi,
                                                            bf16* __restrict__ olo) {
    const int unit = blockIdx.x * 8 + (threadIdx.x >> 5);
    const int lane = threadIdx.x & 31;
    const int g = unit / 6, h = unit % 6;
    const int b = g / Lv, l = g % Lv;
    const long base0 = ((long)(b * 8) * Lv + l) * 576 + h * 32 + lane;
    const long tstride = (long)Lv * 576;

    float q[8], k[8], v[8];
#pragma unroll
    for (int t = 0; t < 8; t++) {
        long base = base0 + (long)t * tstride;
        q[t] = qkv[base];
        k[t] = qkv[base + 192];
        v[t] = qkv[base + 384];
    }
#pragma unroll
    for (int t1 = 0; t1 < 8; t1++) {
        float s[8];
#pragma unroll
        for (int t2 = 0; t2 < 8; t2++) s[t2] = q[t1] * k[t2];
#pragma unroll
        for (int o = 16; o > 0; o >>= 1) {
#pragma unroll
            for (int t2 = 0; t2 < 8; t2++) s[t2] += __shfl_xor_sync(~0u, s[t2], o);
        }
        float mx = s[0];
#pragma unroll
        for (int t2 = 1; t2 < 8; t2++) mx = fmaxf(mx, s[t2]);
        float sum = 0.f;
#pragma unroll
        for (int t2 = 0; t2 < 8; t2++) { s[t2] = __expf(s[t2] - mx); sum += s[t2]; }
        float inv = 1.0f / sum;
        float o = 0.f;
#pragma unroll
        for (int t2 = 0; t2 < 8; t2++) o += s[t2] * v[t2];
        o *= inv;
        long e = ((long)(b * 8 + t1) * Lv + l) * 192 + h * 32 + lane;
        bf16 hb = __float2bfloat16(o);
        ohi[e] = hb;
        olo[e] = __float2bfloat16(o - __bfloat162float(hb));
    }
}

// ---------------- launcher ----------------
extern "C" void kernel_launch(void* const* d_in, const int* in_sizes, int n_in,
                              void* d_out, int out_size) {
    (void)in_sizes; (void)n_in;
    const float* x        = (const float*)d_in[0];
    const float* norm1_g  = (const float*)d_in[2];
    const float* norm1_b  = (const float*)d_in[3];
    const float* qkv_w    = (const float*)d_in[4];
    const float* qkv_b    = (const float*)d_in[5];
    const float* proj_sp_w = (const float*)d_in[6];
    const float* proj_sp_b = (const float*)d_in[7];
    const float* proj_t_w = (const float*)d_in[8];
    const float* proj_t_b = (const float*)d_in[9];
    const float* norm2_g  = (const float*)d_in[10];
    const float* norm2_b  = (const float*)d_in[11];
    const float* te_fc1_w = (const float*)d_in[12];
    const float* te_fc1_b = (const float*)d_in[13];
    const float* te_fc2_w = (const float*)d_in[14];
    const float* te_fc2_b = (const float*)d_in[15];
    const float* sp_fc1_w = (const float*)d_in[16];
    const float* sp_fc1_b = (const float*)d_in[17];
    const float* sp_fc2_w = (const float*)d_in[18];
    const float* sp_fc2_b = (const float*)d_in[19];
    const float* fuse_w   = (const float*)d_in[20];
    const float* fuse_b   = (const float*)d_in[21];

    float* out = (float*)d_out;
    float *xt, *xsp;
    if ((long)out_size >= 3 * MCl) {
        xt = out + MCl;
        xsp = out + 2 * MCl;
    } else {
        void* p;
        cudaGetSymbolAddress(&p, g_xt_fb);  xt = (float*)p;
        cudaGetSymbolAddress(&p, g_xsp_fb); xsp = (float*)p;
    }
    void* p;
    cudaGetSymbolAddress(&p, g_qkv);    float* qkv = (float*)p;
    cudaGetSymbolAddress(&p, g_a_hi);   bf16* a_hi = (bf16*)p;
    cudaGetSymbolAddress(&p, g_a_lo);   bf16* a_lo = (bf16*)p;
    cudaGetSymbolAddress(&p, g_osp_hi); bf16* osp_hi = (bf16*)p;
    cudaGetSymbolAddress(&p, g_osp_lo); bf16* osp_lo = (bf16*)p;
    cudaGetSymbolAddress(&p, g_ot_hi);  bf16* ot_hi = (bf16*)p;
    cudaGetSymbolAddress(&p, g_ot_lo);  bf16* ot_lo = (bf16*)p;
    cudaGetSymbolAddress(&p, g_h_hi);   bf16* h_hi = (bf16*)p;
    cudaGetSymbolAddress(&p, g_h_lo);   bf16* h_lo = (bf16*)p;
    cudaGetSymbolAddress(&p, g_cat_hi); bf16* cat_hi = (bf16*)p;
    cudaGetSymbolAddress(&p, g_cat_lo); bf16* cat_lo = (bf16*)p;
    cudaGetSymbolAddress(&p, g_whi);    bf16* whi = (bf16*)p;
    cudaGetSymbolAddress(&p, g_wlo);    bf16* wlo = (bf16*)p;

    cudaFuncSetAttribute(mma_gemm<192, 1>, cudaFuncAttributeMaxDynamicSharedMemorySize, DSMEM);
    cudaFuncSetAttribute(mma_gemm<192, 2>, cudaFuncAttributeMaxDynamicSharedMemorySize, DSMEM);
    cudaFuncSetAttribute(mma_gemm<192, 4>, cudaFuncAttributeMaxDynamicSharedMemorySize, DSMEM);
    cudaFuncSetAttribute(mma_gemm<768, 2>, cudaFuncAttributeMaxDynamicSharedMemorySize, DSMEM);
    cudaFuncSetAttribute(mma_gemm<384, 0>, cudaFuncAttributeMaxDynamicSharedMemorySize, DSMEM);

    const int MT = Mv / 128;  // 1568

    // weight preconversion
    w_conv_all_kernel<<<(847872 + 255) / 256, 256>>>(
        qkv_w, proj_sp_w, proj_t_w, te_fc1_w, te_fc2_w, sp_fc1_w, sp_fc2_w, fuse_w, whi, wlo);
    // LN1 apply
    ln_apply_kernel<<<Mv / 8, 256>>>(x, norm1_g, norm1_b, a_hi, a_lo);
    // QKV (N=576)
    mma_gemm<192, 1><<<dim3(MT, 6), 256, DSMEM>>>(
        a_hi, a_lo, whi + WO_QKV, wlo + WO_QKV, qkv_b, nullptr,
        qkv, nullptr, nullptr, nullptr, nullptr, 0, 576);
    // attention
    attn_spatial_kernel<<<4096 * 6, 128>>>(qkv, osp_hi, osp_lo);
    attn_temporal_kernel<<<(Bv * Lv * 6) / 8, 256>>>(qkv, ot_hi, ot_lo);
    // proj + residual
    mma_gemm<192, 2><<<dim3(MT, 2), 256, DSMEM>>>(
        osp_hi, osp_lo, whi + WO_PSP, wlo + WO_PSP, proj_sp_b, x,
        xsp, nullptr, nullptr, nullptr, nullptr, 0, 192);
    mma_gemm<192, 2><<<dim3(MT, 2), 256, DSMEM>>>(
        ot_hi, ot_lo, whi + WO_PT, wlo + WO_PT, proj_t_b, x,
        xt, nullptr, nullptr, nullptr, nullptr, 0, 192);
    // temporal MLP (fc2 epilogue also emits bf16 concat slot 0)
    ln_apply_kernel<<<Mv / 8, 256>>>(xt, norm2_g, norm2_b, a_hi, a_lo);
    mma_gemm<192, 4><<<dim3(MT, 8), 256, DSMEM>>>(
        a_hi, a_lo, whi + WO_TF1, wlo + WO_TF1, te_fc1_b, nullptr,
        nullptr, h_hi, h_lo, nullptr, nullptr, 0, HIDv);
    mma_gemm<768, 2><<<dim3(MT, 2), 256, DSMEM>>>(
        h_hi, h_lo, whi + WO_TF2, wlo + WO_TF2, te_fc2_b, xt,
        xt, nullptr, nullptr, cat_hi, cat_lo, 0, 192);
    // spatial MLP (fc2 epilogue emits concat slot 192)
    ln_apply_kernel<<<Mv / 8, 256>>>(xsp, norm2_g, norm2_b, a_hi, a_lo);
    mma_gemm<192, 4><<<dim3(MT, 8), 256, DSMEM>>>(
        a_hi, a_lo, whi + WO_SF1, wlo + WO_SF1, sp_fc1_b, nullptr,
        nullptr, h_hi, h_lo, nullptr, nullptr, 0, HIDv);
    mma_gemm<768, 2><<<dim3(MT, 2), 256, DSMEM>>>(
        h_hi, h_lo, whi + WO_SF2, wlo + WO_SF2, sp_fc2_b, xsp,
        xsp, nullptr, nullptr, cat_hi, cat_lo, 192, 192);
    // fuse: out = cat @ fuse_w^T + b
    mma_gemm<384, 0><<<dim3(MT, 2), 256, DSMEM>>>(
        cat_hi, cat_lo, whi + WO_FUSE, wlo + WO_FUSE, fuse_b, nullptr,
        out, nullptr, nullptr, nullptr, nullptr, 0, 192);
}

// round 8
// speedup vs baseline: 1.5516x; 1.3447x over previous
#include <cuda_runtime.h>
#include <cuda_fp16.h>
#include <math.h>
#include <stdint.h>

// ---------------- problem constants ----------------
constexpr int Bv = 8, Tv = 8, Hv = 56, Wv = 56, Cv = 192;
constexpr int NHv = 6, Lv = Hv * Wv;                // 3136
constexpr int HIDv = 4 * Cv;                        // 768
constexpr int Mv = Bv * Tv * Lv;                    // 200704 tokens
constexpr long MCl = (long)Mv * Cv;
constexpr float QSCALE = 0.17677669529663687f;      // 32^-0.5

// ---------------- device scratch ----------------
__device__ float g_qkv[(long)Mv * 576];
__device__ __half g_a[MCl];
__device__ __half g_osp[MCl];
__device__ __half g_ot[MCl];
__device__ __half g_h[(long)Mv * HIDv];
__device__ __half g_cat[(long)Mv * 384];
__device__ __half g_whi[847872], g_wlo[847872];
__device__ float g_xt_fb[MCl];
__device__ float g_xsp_fb[MCl];

// weight offsets
constexpr int WO_QKV = 0;            // 576x192
constexpr int WO_PSP = 110592;       // 192x192
constexpr int WO_PT  = 147456;       // 192x192
constexpr int WO_TF1 = 184320;       // 768x192
constexpr int WO_TF2 = 331776;       // 192x768
constexpr int WO_SF1 = 479232;       // 768x192
constexpr int WO_SF2 = 626688;       // 192x768
constexpr int WO_FUSE = 774144;      // 192x384

// ---------------- helpers ----------------
__device__ __forceinline__ uint32_t smem_u32(const void* p) {
    uint32_t a;
    asm("{ .reg .u64 t; cvta.to.shared.u64 t, %1; cvt.u32.u64 %0, t; }" : "=r"(a) : "l"(p));
    return a;
}
__device__ __forceinline__ uint32_t pack_h2(float x, float y) {
    __half2 h = __floats2half2_rn(x, y);
    return *reinterpret_cast<uint32_t*>(&h);
}

#define LDSM4(r, addr)                                                        \
    asm volatile("ldmatrix.sync.aligned.m8n8.x4.shared.b16 {%0,%1,%2,%3}, [%4];" \
        : "=r"((r)[0]), "=r"((r)[1]), "=r"((r)[2]), "=r"((r)[3]) : "r"(addr))

#define MMA_F16(c, a, b0, b1)                                                 \
    asm volatile("mma.sync.aligned.m16n8k16.row.col.f32.f16.f16.f32 "         \
        "{%0,%1,%2,%3},{%4,%5,%6,%7},{%8,%9},{%0,%1,%2,%3};"                  \
        : "+f"((c)[0]), "+f"((c)[1]), "+f"((c)[2]), "+f"((c)[3])              \
        : "r"((a)[0]), "r"((a)[1]), "r"((a)[2]), "r"((a)[3]), "r"(b0), "r"(b1))

#define CP16(smem, gptr)                                                      \
    asm volatile("cp.async.cg.shared.global [%0], [%1], 16;"                  \
        :: "r"(smem), "l"(gptr) : "memory")
#define CP_COMMIT() asm volatile("cp.async.commit_group;" ::: "memory")
#define CP_WAIT1()  asm volatile("cp.async.wait_group 1;" ::: "memory")

// ---------------- fp16 2-term pipelined GEMM, CTA tile 128x96, 3-stage ring ----------------
// smem stage (80B rows): A 0 (128x64B) | Whi 10240 (96x64B) | Wlo 17920; stage 25600
// EM: 0 bias; 1 +qscale(cols<192); 2 +residual (+optional fp16 concat); 4 +GELU -> fp16 out
constexpr int STAGE = 25600;
constexpr int NSTG = 3;
constexpr int DSMEM = NSTG * STAGE;

template <int KD, int EM>
__global__ void __launch_bounds__(256, 2)
mma_gemm(const __half* __restrict__ A,
         const __half* __restrict__ Whi, const __half* __restrict__ Wlo,
         const float* __restrict__ bias, const float* __restrict__ R,
         float* __restrict__ Y, __half* __restrict__ Yh,
         __half* __restrict__ Cat, int catoff, int N) {
    extern __shared__ char sm[];
    const int tid = threadIdx.x;
    const long m0 = (long)blockIdx.x * 128;
    const int n0 = blockIdx.y * 96;
    constexpr int NS = KD / 32;
    const uint32_t smb = smem_u32(sm);

    // cp.async mapping: A 2 thr/row (128 rows, 64B), W 2 thr/row for tid<192 (96 rows, 2 planes)
    const int ar = tid >> 1, aoff = (tid & 1) * 32;
    const int br = tid >> 1, boff = (tid & 1) * 32;
    const bool bact = tid < 192;

    auto fill = [&](int s) {
        const int buf = s % NSTG;
        const uint32_t sb = smb + buf * STAGE;
        {
            const char* g = reinterpret_cast<const char*>(A + (m0 + ar) * (long)KD + s * 32) + aoff;
            uint32_t d = sb + ar * 80 + aoff;
            CP16(d, g); CP16(d + 16, g + 16);
        }
        if (bact) {
            const char* g = reinterpret_cast<const char*>(Whi + (long)(n0 + br) * KD + s * 32) + boff;
            uint32_t d = sb + 10240 + br * 80 + boff;
            CP16(d, g); CP16(d + 16, g + 16);
            const char* g2 = reinterpret_cast<const char*>(Wlo + (long)(n0 + br) * KD + s * 32) + boff;
            uint32_t d2 = sb + 17920 + br * 80 + boff;
            CP16(d2, g2); CP16(d2 + 16, g2 + 16);
        }
    };

    // mma mapping: 8 warps = 4(M) x 2(N); warp tile 32x48
    const int l = tid & 31, wid = tid >> 5;
    const int wm = wid & 3, wn = wid >> 2;
    const int arow = wm * 32 + (l & 15);
    const int acol8 = (l >> 4) * 8;
    const int brow = wn * 48 + (l & 7) + ((l >> 4) << 3);
    const int bcol8 = ((l >> 3) & 1) * 8;

    float acc[2][6][4];
#pragma unroll
    for (int i = 0; i < 2; i++)
#pragma unroll
        for (int j = 0; j < 6; j++)
#pragma unroll
            for (int k = 0; k < 4; k++) acc[i][j][k] = 0.f;

    auto mmastage = [&](int buf) {
        const uint32_t base = smb + buf * STAGE;
#pragma unroll
        for (int kt = 0; kt < 2; kt++) {
            uint32_t af[2][4];
#pragma unroll
            for (int mt = 0; mt < 2; mt++)
                LDSM4(af[mt], base + (arow + mt * 16) * 80 + (kt * 16 + acol8) * 2);
#pragma unroll
            for (int nt = 0; nt < 3; nt++) {
                uint32_t bhf[4], blf[4];
                uint32_t addr = base + 10240 + (brow + nt * 16) * 80 + (kt * 16 + bcol8) * 2;
                LDSM4(bhf, addr);
                LDSM4(blf, addr + 7680);
#pragma unroll
                for (int mt = 0; mt < 2; mt++)
#pragma unroll
                    for (int jj = 0; jj < 2; jj++) {
                        const int nn = nt * 2 + jj;
                        MMA_F16(acc[mt][nn], af[mt], bhf[2 * jj], bhf[2 * jj + 1]);
                        MMA_F16(acc[mt][nn], af[mt], blf[2 * jj], blf[2 * jj + 1]);
                    }
            }
        }
    };

    fill(0); CP_COMMIT();
    fill(1); CP_COMMIT();
    for (int s = 0; s < NS; s++) {
        CP_WAIT1();
        __syncthreads();
        mmastage(s % NSTG);
        if (s + 2 < NS) fill(s + 2);
        CP_COMMIT();
    }

    // register epilogue
    const int g = l >> 2, tg = l & 3;
#pragma unroll
    for (int mt = 0; mt < 2; mt++)
#pragma unroll
        for (int nn = 0; nn < 6; nn++) {
            const int col = n0 + wn * 48 + nn * 8 + 2 * tg;
            const float b0 = bias[col], b1 = bias[col + 1];
#pragma unroll
            for (int h = 0; h < 2; h++) {
                const long row = m0 + wm * 32 + mt * 16 + g + 8 * h;
                float vx = acc[mt][nn][2 * h] + b0;
                float vy = acc[mt][nn][2 * h + 1] + b1;
                if (EM == 1) {
                    if (col < 192) { vx *= QSCALE; vy *= QSCALE; }
                    *reinterpret_cast<float2*>(Y + row * (long)N + col) = make_float2(vx, vy);
                }
                if (EM == 0) {
                    *reinterpret_cast<float2*>(Y + row * (long)N + col) = make_float2(vx, vy);
                }
                if (EM == 2) {
                    float2 rv = *reinterpret_cast<const float2*>(R + row * (long)N + col);
                    vx += rv.x; vy += rv.y;
                    *reinterpret_cast<float2*>(Y + row * (long)N + col) = make_float2(vx, vy);
                    if (Cat) {
                        reinterpret_cast<uint32_t*>(Cat)[(row * 384 + catoff + col) >> 1] =
                            pack_h2(vx, vy);
                    }
                }
                if (EM == 4) {
                    vx = 0.5f * vx * (1.0f + erff(vx * 0.70710678118654752f));
                    vy = 0.5f * vy * (1.0f + erff(vy * 0.70710678118654752f));
                    reinterpret_cast<uint32_t*>(Yh)[(row * (long)N + col) >> 1] = pack_h2(vx, vy);
                }
            }
        }
}

// ---------------- combined weight preconversion (fp16 hi/lo) ----------------
__global__ void w_conv_all_kernel(const float* qkv_w, const float* psp_w, const float* pt_w,
                                  const float* tf1_w, const float* tf2_w, const float* sf1_w,
                                  const float* sf2_w, const float* fuse_w,
                                  __half* __restrict__ hi, __half* __restrict__ lo) {
    int i = blockIdx.x * 256 + threadIdx.x;
    if (i >= 847872) return;
    float v;
    if (i < WO_PSP)       v = qkv_w[i - WO_QKV];
    else if (i < WO_PT)   v = psp_w[i - WO_PSP];
    else if (i < WO_TF1)  v = pt_w[i - WO_PT];
    else if (i < WO_TF2)  v = tf1_w[i - WO_TF1];
    else if (i < WO_SF1)  v = tf2_w[i - WO_TF2];
    else if (i < WO_SF2)  v = sf1_w[i - WO_SF1];
    else if (i < WO_FUSE) v = sf2_w[i - WO_SF2];
    else                  v = fuse_w[i - WO_FUSE];
    __half h = __float2half_rn(v);
    hi[i] = h;
    lo[i] = __float2half_rn(v - __half2float(h));
}

// ---------------- LN fused stats+apply -> fp16 ----------------
__global__ void ln_apply_kernel(const float* __restrict__ X,
                                const float* __restrict__ gamma, const float* __restrict__ beta,
                                __half* __restrict__ O) {
    int tok = blockIdx.x * 8 + (threadIdx.x >> 5);
    int lane = threadIdx.x & 31;
    const float* p = X + (long)tok * Cv;
    float v[6];
#pragma unroll
    for (int i = 0; i < 6; i++) v[i] = p[lane + i * 32];
    float s = v[0] + v[1] + v[2] + v[3] + v[4] + v[5];
#pragma unroll
    for (int o = 16; o > 0; o >>= 1) s += __shfl_xor_sync(~0u, s, o);
    float mu = s * (1.0f / Cv);
    float qv = 0.f;
#pragma unroll
    for (int i = 0; i < 6; i++) { float d = v[i] - mu; qv += d * d; }
#pragma unroll
    for (int o = 16; o > 0; o >>= 1) qv += __shfl_xor_sync(~0u, qv, o);
    float rs = rsqrtf(qv * (1.0f / Cv) + 1e-5f);
#pragma unroll
    for (int i = 0; i < 6; i++) {
        int c = lane + i * 32;
        O[(long)tok * Cv + c] = __float2half_rn((v[i] - mu) * rs * gamma[c] + beta[c]);
    }
}

// ---------------- spatial window attention -> fp16 ----------------
__global__ void __launch_bounds__(128) attn_spatial_kernel(const float* __restrict__ qkv,
                                                           __half* __restrict__ O) {
    __shared__ float qs[49][33], ks[49][33], vs[49][33];
    __shared__ float sc[49][52];
    const int gh = blockIdx.x;
    const int g = gh / 6, h = gh % 6;
    const int b = g >> 9;
    const int rem = g & 511;
    const int win = rem >> 3, t = rem & 7;
    const int wh = win >> 3, ww = win & 7;
    const int tid = threadIdx.x;
    const long frame = (long)(b * 8 + t) * Lv;

    for (int idx = tid; idx < 49 * 32; idx += 128) {
        int i = idx >> 5, j = idx & 31;
        int l = (wh * 7 + i / 7) * 56 + ww * 7 + (i % 7);
        long base = (frame + l) * 576 + h * 32 + j;
        qs[i][j] = qkv[base];
        ks[i][j] = qkv[base + 192];
        vs[i][j] = qkv[base + 384];
    }
    __syncthreads();

    for (int u = tid; u < 49 * 13; u += 128) {
        int i = u / 13, jb = (u % 13) * 4;
        float a0 = 0.f, a1 = 0.f, a2 = 0.f, a3 = 0.f;
        int j1 = jb + 1 < 49 ? jb + 1 : 48;
        int j2 = jb + 2 < 49 ? jb + 2 : 48;
        int j3 = jb + 3 < 49 ? jb + 3 : 48;
#pragma unroll
        for (int kk = 0; kk < 32; kk++) {
            float qv = qs[i][kk];
            a0 += qv * ks[jb][kk];
            a1 += qv * ks[j1][kk];
            a2 += qv * ks[j2][kk];
            a3 += qv * ks[j3][kk];
        }
        sc[i][jb] = a0;
        if (jb + 1 < 49) sc[i][jb + 1] = a1;
        if (jb + 2 < 49) sc[i][jb + 2] = a2;
        if (jb + 3 < 49) sc[i][jb + 3] = a3;
    }
    __syncthreads();

    if (tid < 49) {
        float mx = -1e30f;
#pragma unroll 7
        for (int j = 0; j < 49; j++) mx = fmaxf(mx, sc[tid][j]);
        float sum = 0.f;
#pragma unroll 7
        for (int j = 0; j < 49; j++) { float e = __expf(sc[tid][j] - mx); sc[tid][j] = e; sum += e; }
        float inv = 1.0f / sum;
#pragma unroll 7
        for (int j = 0; j < 49; j++) sc[tid][j] *= inv;
    }
    __syncthreads();

    for (int u = tid; u < 49 * 8; u += 128) {
        int i = u >> 3, jb = (u & 7) * 4;
        float a0 = 0.f, a1 = 0.f, a2 = 0.f, a3 = 0.f;
#pragma unroll
        for (int n = 0; n < 49; n++) {
            float s = sc[i][n];
            a0 += s * vs[n][jb + 0];
            a1 += s * vs[n][jb + 1];
            a2 += s * vs[n][jb + 2];
            a3 += s * vs[n][jb + 3];
        }
        int l = (wh * 7 + i / 7) * 56 + ww * 7 + (i % 7);
        long idx = (frame + l) * 192 + h * 32 + jb;
        *reinterpret_cast<uint2*>(O + idx) = make_uint2(pack_h2(a0, a1), pack_h2(a2, a3));
    }
}

// ---------------- temporal attention -> fp16 ----------------
__global__ void __launch_bounds__(256) attn_temporal_kernel(const float* __restrict__ qkv,
                                                            __half* __restrict__ O) {
    const int unit = blockIdx.x * 8 + (threadIdx.x >> 5);
    const int lane = threadIdx.x & 31;
    const int g = unit / 6, h = unit % 6;
    const int b = g / Lv, l = g % Lv;
    const long base0 = ((long)(b * 8) * Lv + l) * 576 + h * 32 + lane;
    const long tstride = (long)Lv * 576;

    float q[8], k[8], v[8];
#pragma unroll
    for (int t = 0; t < 8; t++) {
        long base = base0 + (long)t * tstride;
        q[t] = qkv[base];
        k[t] = qkv[base + 192];
        v[t] = qkv[base + 384];
    }
#pragma unroll
    for (int t1 = 0; t1 < 8; t1++) {
        float s[8];
#pragma unroll
        for (int t2 = 0; t2 < 8; t2++) s[t2] = q[t1] * k[t2];
#pragma unroll
        for (int o = 16; o > 0; o >>= 1) {
#pragma unroll
            for (int t2 = 0; t2 < 8; t2++) s[t2] += __shfl_xor_sync(~0u, s[t2], o);
        }
        float mx = s[0];
#pragma unroll
        for (int t2 = 1; t2 < 8; t2++) mx = fmaxf(mx, s[t2]);
        float sum = 0.f;
#pragma unroll
        for (int t2 = 0; t2 < 8; t2++) { s[t2] = __expf(s[t2] - mx); sum += s[t2]; }
        float inv = 1.0f / sum;
        float o = 0.f;
#pragma unroll
        for (int t2 = 0; t2 < 8; t2++) o += s[t2] * v[t2];
        O[((long)(b * 8 + t1) * Lv + l) * 192 + h * 32 + lane] = __float2half_rn(o * inv);
    }
}

// ---------------- launcher ----------------
extern "C" void kernel_launch(void* const* d_in, const int* in_sizes, int n_in,
                              void* d_out, int out_size) {
    (void)in_sizes; (void)n_in;
    const float* x        = (const float*)d_in[0];
    const float* norm1_g  = (const float*)d_in[2];
    const float* norm1_b  = (const float*)d_in[3];
    const float* qkv_w    = (const float*)d_in[4];
    const float* qkv_b    = (const float*)d_in[5];
    const float* proj_sp_w = (const float*)d_in[6];
    const float* proj_sp_b = (const float*)d_in[7];
    const float* proj_t_w = (const float*)d_in[8];
    const float* proj_t_b = (const float*)d_in[9];
    const float* norm2_g  = (const float*)d_in[10];
    const float* norm2_b  = (const float*)d_in[11];
    const float* te_fc1_w = (const float*)d_in[12];
    const float* te_fc1_b = (const float*)d_in[13];
    const float* te_fc2_w = (const float*)d_in[14];
    const float* te_fc2_b = (const float*)d_in[15];
    const float* sp_fc1_w = (const float*)d_in[16];
    const float* sp_fc1_b = (const float*)d_in[17];
    const float* sp_fc2_w = (const float*)d_in[18];
    const float* sp_fc2_b = (const float*)d_in[19];
    const float* fuse_w   = (const float*)d_in[20];
    const float* fuse_b   = (const float*)d_in[21];

    float* out = (float*)d_out;
    float *xt, *xsp;
    if ((long)out_size >= 3 * MCl) {
        xt = out + MCl;
        xsp = out + 2 * MCl;
    } else {
        void* p;
        cudaGetSymbolAddress(&p, g_xt_fb);  xt = (float*)p;
        cudaGetSymbolAddress(&p, g_xsp_fb); xsp = (float*)p;
    }
    void* p;
    cudaGetSymbolAddress(&p, g_qkv);  float* qkv = (float*)p;
    cudaGetSymbolAddress(&p, g_a);    __half* a = (__half*)p;
    cudaGetSymbolAddress(&p, g_osp);  __half* osp = (__half*)p;
    cudaGetSymbolAddress(&p, g_ot);   __half* ot = (__half*)p;
    cudaGetSymbolAddress(&p, g_h);    __half* hb = (__half*)p;
    cudaGetSymbolAddress(&p, g_cat);  __half* cat = (__half*)p;
    cudaGetSymbolAddress(&p, g_whi);  __half* whi = (__half*)p;
    cudaGetSymbolAddress(&p, g_wlo);  __half* wlo = (__half*)p;

    cudaFuncSetAttribute(mma_gemm<192, 1>, cudaFuncAttributeMaxDynamicSharedMemorySize, DSMEM);
    cudaFuncSetAttribute(mma_gemm<192, 2>, cudaFuncAttributeMaxDynamicSharedMemorySize, DSMEM);
    cudaFuncSetAttribute(mma_gemm<192, 4>, cudaFuncAttributeMaxDynamicSharedMemorySize, DSMEM);
    cudaFuncSetAttribute(mma_gemm<768, 2>, cudaFuncAttributeMaxDynamicSharedMemorySize, DSMEM);
    cudaFuncSetAttribute(mma_gemm<384, 0>, cudaFuncAttributeMaxDynamicSharedMemorySize, DSMEM);

    const int MT = Mv / 128;  // 1568

    w_conv_all_kernel<<<(847872 + 255) / 256, 256>>>(
        qkv_w, proj_sp_w, proj_t_w, te_fc1_w, te_fc2_w, sp_fc1_w, sp_fc2_w, fuse_w, whi, wlo);
    ln_apply_kernel<<<Mv / 8, 256>>>(x, norm1_g, norm1_b, a);
    // QKV (N=576)
    mma_gemm<192, 1><<<dim3(MT, 6), 256, DSMEM>>>(
        a, whi + WO_QKV, wlo + WO_QKV, qkv_b, nullptr, qkv, nullptr, nullptr, 0, 576);
    // attention
    attn_spatial_kernel<<<4096 * 6, 128>>>(qkv, osp);
    attn_temporal_kernel<<<(Bv * Lv * 6) / 8, 256>>>(qkv, ot);
    // proj + residual
    mma_gemm<192, 2><<<dim3(MT, 2), 256, DSMEM>>>(
        osp, whi + WO_PSP, wlo + WO_PSP, proj_sp_b, x, xsp, nullptr, nullptr, 0, 192);
    mma_gemm<192, 2><<<dim3(MT, 2), 256, DSMEM>>>(
        ot, whi + WO_PT, wlo + WO_PT, proj_t_b, x, xt, nullptr, nullptr, 0, 192);
    // temporal MLP (fc2 also emits concat slot 0)
    ln_apply_kernel<<<Mv / 8, 256>>>(xt, norm2_g, norm2_b, a);
    mma_gemm<192, 4><<<dim3(MT, 8), 256, DSMEM>>>(
        a, whi + WO_TF1, wlo + WO_TF1, te_fc1_b, nullptr, nullptr, hb, nullptr, 0, HIDv);
    mma_gemm<768, 2><<<dim3(MT, 2), 256, DSMEM>>>(
        hb, whi + WO_TF2, wlo + WO_TF2, te_fc2_b, xt, xt, nullptr, cat, 0, 192);
    // spatial MLP (fc2 emits concat slot 192)
    ln_apply_kernel<<<Mv / 8, 256>>>(xsp, norm2_g, norm2_b, a);
    mma_gemm<192, 4><<<dim3(MT, 8), 256, DSMEM>>>(
        a, whi + WO_SF1, wlo + WO_SF1, sp_fc1_b, nullptr, nullptr, hb, nullptr, 0, HIDv);
    mma_gemm<768, 2><<<dim3(MT, 2), 256, DSMEM>>>(
        hb, whi + WO_SF2, wlo + WO_SF2, sp_fc2_b, xsp, xsp, nullptr, cat, 192, 192);
    // fuse
    mma_gemm<384, 0><<<dim3(MT, 2), 256, DSMEM>>>(
        cat, whi + WO_FUSE, wlo + WO_FUSE, fuse_b, nullptr, out, nullptr, nullptr, 0, 192);
}

// round 9
// speedup vs baseline: 1.8502x; 1.1925x over previous
#include <cuda_runtime.h>
#include <cuda_fp16.h>
#include <math.h>
#include <stdint.h>

// ---------------- problem constants ----------------
constexpr int Bv = 8, Tv = 8, Hv = 56, Wv = 56, Cv = 192;
constexpr int NHv = 6, Lv = Hv * Wv;                // 3136
constexpr int HIDv = 4 * Cv;                        // 768
constexpr int Mv = Bv * Tv * Lv;                    // 200704 tokens
constexpr long MCl = (long)Mv * Cv;
constexpr float QSCALE = 0.17677669529663687f;      // 32^-0.5

// ---------------- device scratch ----------------
__device__ __half g_qkv[(long)Mv * 576];
__device__ __half g_a[MCl];
__device__ __half g_osp[MCl];
__device__ __half g_ot[MCl];
__device__ __half g_h[(long)Mv * HIDv];
__device__ __half g_cat[(long)Mv * 384];
__device__ __half g_whi[847872];
__device__ float g_xt_fb[MCl];
__device__ float g_xsp_fb[MCl];

// weight offsets
constexpr int WO_QKV = 0;            // 576x192
constexpr int WO_PSP = 110592;       // 192x192
constexpr int WO_PT  = 147456;       // 192x192
constexpr int WO_TF1 = 184320;       // 768x192
constexpr int WO_TF2 = 331776;       // 192x768
constexpr int WO_SF1 = 479232;       // 768x192
constexpr int WO_SF2 = 626688;       // 192x768
constexpr int WO_FUSE = 774144;      // 192x384

// ---------------- helpers ----------------
__device__ __forceinline__ uint32_t smem_u32(const void* p) {
    uint32_t a;
    asm("{ .reg .u64 t; cvta.to.shared.u64 t, %1; cvt.u32.u64 %0, t; }" : "=r"(a) : "l"(p));
    return a;
}
__device__ __forceinline__ uint32_t pack_h2(float x, float y) {
    __half2 h = __floats2half2_rn(x, y);
    return *reinterpret_cast<uint32_t*>(&h);
}

#define LDSM4(r, addr)                                                        \
    asm volatile("ldmatrix.sync.aligned.m8n8.x4.shared.b16 {%0,%1,%2,%3}, [%4];" \
        : "=r"((r)[0]), "=r"((r)[1]), "=r"((r)[2]), "=r"((r)[3]) : "r"(addr))

#define MMA_F16(c, a, b0, b1)                                                 \
    asm volatile("mma.sync.aligned.m16n8k16.row.col.f32.f16.f16.f32 "         \
        "{%0,%1,%2,%3},{%4,%5,%6,%7},{%8,%9},{%0,%1,%2,%3};"                  \
        : "+f"((c)[0]), "+f"((c)[1]), "+f"((c)[2]), "+f"((c)[3])              \
        : "r"((a)[0]), "r"((a)[1]), "r"((a)[2]), "r"((a)[3]), "r"(b0), "r"(b1))

#define CP16(smem, gptr)                                                      \
    asm volatile("cp.async.cg.shared.global [%0], [%1], 16;"                  \
        :: "r"(smem), "l"(gptr) : "memory")
#define CP_COMMIT() asm volatile("cp.async.commit_group;" ::: "memory")
#define CP_WAIT1()  asm volatile("cp.async.wait_group 1;" ::: "memory")

// ---------------- fp16 pipelined GEMM, CTA tile 128x96, 3-stage ring ----------------
// smem stage (80B rows): A 0 (128x64B) | W 10240 (96x64B); stage 17920
// EM: 0 bias->fp32; 1 +qscale(cols<192)->fp16; 2 +residual->fp32 (+opt fp16 concat);
//     4 +GELU->fp16
constexpr int STAGE = 17920;
constexpr int NSTG = 3;
constexpr int DSMEM = NSTG * STAGE;

template <int KD, int EM>
__global__ void __launch_bounds__(256, 2)
mma_gemm(const __half* __restrict__ A, const __half* __restrict__ W,
         const float* __restrict__ bias, const float* __restrict__ R,
         float* __restrict__ Y, __half* __restrict__ Yh,
         __half* __restrict__ Cat, int catoff, int N) {
    extern __shared__ char sm[];
    const int tid = threadIdx.x;
    const long m0 = (long)blockIdx.x * 128;
    const int n0 = blockIdx.y * 96;
    constexpr int NS = KD / 32;
    const uint32_t smb = smem_u32(sm);

    const int ar = tid >> 1, aoff = (tid & 1) * 32;
    const int br = tid >> 1, boff = (tid & 1) * 32;
    const bool bact = tid < 192;

    auto fill = [&](int s) {
        const int buf = s % NSTG;
        const uint32_t sb = smb + buf * STAGE;
        {
            const char* g = reinterpret_cast<const char*>(A + (m0 + ar) * (long)KD + s * 32) + aoff;
            uint32_t d = sb + ar * 80 + aoff;
            CP16(d, g); CP16(d + 16, g + 16);
        }
        if (bact) {
            const char* g = reinterpret_cast<const char*>(W + (long)(n0 + br) * KD + s * 32) + boff;
            uint32_t d = sb + 10240 + br * 80 + boff;
            CP16(d, g); CP16(d + 16, g + 16);
        }
    };

    // mma mapping: 8 warps = 4(M) x 2(N); warp tile 32x48
    const int l = tid & 31, wid = tid >> 5;
    const int wm = wid & 3, wn = wid >> 2;
    const int arow = wm * 32 + (l & 15);
    const int acol8 = (l >> 4) * 8;
    const int brow = wn * 48 + (l & 7) + ((l >> 4) << 3);
    const int bcol8 = ((l >> 3) & 1) * 8;

    float acc[2][6][4];
#pragma unroll
    for (int i = 0; i < 2; i++)
#pragma unroll
        for (int j = 0; j < 6; j++)
#pragma unroll
            for (int k = 0; k < 4; k++) acc[i][j][k] = 0.f;

    auto mmastage = [&](int buf) {
        const uint32_t base = smb + buf * STAGE;
#pragma unroll
        for (int kt = 0; kt < 2; kt++) {
            uint32_t af[2][4];
#pragma unroll
            for (int mt = 0; mt < 2; mt++)
                LDSM4(af[mt], base + (arow + mt * 16) * 80 + (kt * 16 + acol8) * 2);
#pragma unroll
            for (int nt = 0; nt < 3; nt++) {
                uint32_t bf[4];
                LDSM4(bf, base + 10240 + (brow + nt * 16) * 80 + (kt * 16 + bcol8) * 2);
#pragma unroll
                for (int mt = 0; mt < 2; mt++)
#pragma unroll
                    for (int jj = 0; jj < 2; jj++)
                        MMA_F16(acc[mt][nt * 2 + jj], af[mt], bf[2 * jj], bf[2 * jj + 1]);
            }
        }
    };

    fill(0); CP_COMMIT();
    fill(1); CP_COMMIT();
    for (int s = 0; s < NS; s++) {
        CP_WAIT1();
        __syncthreads();
        mmastage(s % NSTG);
        if (s + 2 < NS) fill(s + 2);
        CP_COMMIT();
    }

    // register epilogue
    const int g = l >> 2, tg = l & 3;
#pragma unroll
    for (int mt = 0; mt < 2; mt++)
#pragma unroll
        for (int nn = 0; nn < 6; nn++) {
            const int col = n0 + wn * 48 + nn * 8 + 2 * tg;
            const float b0 = bias[col], b1 = bias[col + 1];
#pragma unroll
            for (int h = 0; h < 2; h++) {
                const long row = m0 + wm * 32 + mt * 16 + g + 8 * h;
                float vx = acc[mt][nn][2 * h] + b0;
                float vy = acc[mt][nn][2 * h + 1] + b1;
                if (EM == 1) {
                    if (col < 192) { vx *= QSCALE; vy *= QSCALE; }
                    reinterpret_cast<uint32_t*>(Yh)[(row * (long)N + col) >> 1] = pack_h2(vx, vy);
                }
                if (EM == 0) {
                    *reinterpret_cast<float2*>(Y + row * (long)N + col) = make_float2(vx, vy);
                }
                if (EM == 2) {
                    float2 rv = *reinterpret_cast<const float2*>(R + row * (long)N + col);
                    vx += rv.x; vy += rv.y;
                    *reinterpret_cast<float2*>(Y + row * (long)N + col) = make_float2(vx, vy);
                    if (Cat) {
                        reinterpret_cast<uint32_t*>(Cat)[(row * 384 + catoff + col) >> 1] =
                            pack_h2(vx, vy);
                    }
                }
                if (EM == 4) {
                    vx = 0.5f * vx * (1.0f + erff(vx * 0.70710678118654752f));
                    vy = 0.5f * vy * (1.0f + erff(vy * 0.70710678118654752f));
                    reinterpret_cast<uint32_t*>(Yh)[(row * (long)N + col) >> 1] = pack_h2(vx, vy);
                }
            }
        }
}

// ---------------- combined weight preconversion (fp16 single plane) ----------------
__global__ void w_conv_all_kernel(const float* qkv_w, const float* psp_w, const float* pt_w,
                                  const float* tf1_w, const float* tf2_w, const float* sf1_w,
                                  const float* sf2_w, const float* fuse_w,
                                  __half* __restrict__ hi) {
    int i = blockIdx.x * 256 + threadIdx.x;
    if (i >= 847872) return;
    float v;
    if (i < WO_PSP)       v = qkv_w[i - WO_QKV];
    else if (i < WO_PT)   v = psp_w[i - WO_PSP];
    else if (i < WO_TF1)  v = pt_w[i - WO_PT];
    else if (i < WO_TF2)  v = tf1_w[i - WO_TF1];
    else if (i < WO_SF1)  v = tf2_w[i - WO_TF2];
    else if (i < WO_SF2)  v = sf1_w[i - WO_SF1];
    else if (i < WO_FUSE) v = sf2_w[i - WO_SF2];
    else                  v = fuse_w[i - WO_FUSE];
    hi[i] = __float2half_rn(v);
}

// ---------------- LN fused stats+apply -> fp16 ----------------
__global__ void ln_apply_kernel(const float* __restrict__ X,
                                const float* __restrict__ gamma, const float* __restrict__ beta,
                                __half* __restrict__ O) {
    int tok = blockIdx.x * 8 + (threadIdx.x >> 5);
    int lane = threadIdx.x & 31;
    const float* p = X + (long)tok * Cv;
    float v[6];
#pragma unroll
    for (int i = 0; i < 6; i++) v[i] = p[lane + i * 32];
    float s = v[0] + v[1] + v[2] + v[3] + v[4] + v[5];
#pragma unroll
    for (int o = 16; o > 0; o >>= 1) s += __shfl_xor_sync(~0u, s, o);
    float mu = s * (1.0f / Cv);
    float qv = 0.f;
#pragma unroll
    for (int i = 0; i < 6; i++) { float d = v[i] - mu; qv += d * d; }
#pragma unroll
    for (int o = 16; o > 0; o >>= 1) qv += __shfl_xor_sync(~0u, qv, o);
    float rs = rsqrtf(qv * (1.0f / Cv) + 1e-5f);
#pragma unroll
    for (int i = 0; i < 6; i++) {
        int c = lane + i * 32;
        O[(long)tok * Cv + c] = __float2half_rn((v[i] - mu) * rs * gamma[c] + beta[c]);
    }
}

// ---------------- spatial window attention (fp16 qkv in) -> fp16 out ----------------
__global__ void __launch_bounds__(128) attn_spatial_kernel(const __half* __restrict__ qkv,
                                                           __half* __restrict__ O) {
    __shared__ float qs[49][33], ks[49][33], vs[49][33];
    __shared__ float sc[49][52];
    const int gh = blockIdx.x;
    const int g = gh / 6, h = gh % 6;
    const int b = g >> 9;
    const int rem = g & 511;
    const int win = rem >> 3, t = rem & 7;
    const int wh = win >> 3, ww = win & 7;
    const int tid = threadIdx.x;
    const long frame = (long)(b * 8 + t) * Lv;

    for (int idx = tid; idx < 49 * 32; idx += 128) {
        int i = idx >> 5, j = idx & 31;
        int l = (wh * 7 + i / 7) * 56 + ww * 7 + (i % 7);
        long base = (frame + l) * 576 + h * 32 + j;
        qs[i][j] = __half2float(qkv[base]);
        ks[i][j] = __half2float(qkv[base + 192]);
        vs[i][j] = __half2float(qkv[base + 384]);
    }
    __syncthreads();

    for (int u = tid; u < 49 * 13; u += 128) {
        int i = u / 13, jb = (u % 13) * 4;
        float a0 = 0.f, a1 = 0.f, a2 = 0.f, a3 = 0.f;
        int j1 = jb + 1 < 49 ? jb + 1 : 48;
        int j2 = jb + 2 < 49 ? jb + 2 : 48;
        int j3 = jb + 3 < 49 ? jb + 3 : 48;
#pragma unroll
        for (int kk = 0; kk < 32; kk++) {
            float qv = qs[i][kk];
            a0 += qv * ks[jb][kk];
            a1 += qv * ks[j1][kk];
            a2 += qv * ks[j2][kk];
            a3 += qv * ks[j3][kk];
        }
        sc[i][jb] = a0;
        if (jb + 1 < 49) sc[i][jb + 1] = a1;
        if (jb + 2 < 49) sc[i][jb + 2] = a2;
        if (jb + 3 < 49) sc[i][jb + 3] = a3;
    }
    __syncthreads();

    if (tid < 49) {
        float mx = -1e30f;
#pragma unroll 7
        for (int j = 0; j < 49; j++) mx = fmaxf(mx, sc[tid][j]);
        float sum = 0.f;
#pragma unroll 7
        for (int j = 0; j < 49; j++) { float e = __expf(sc[tid][j] - mx); sc[tid][j] = e; sum += e; }
        float inv = 1.0f / sum;
#pragma unroll 7
        for (int j = 0; j < 49; j++) sc[tid][j] *= inv;
    }
    __syncthreads();

    for (int u = tid; u < 49 * 8; u += 128) {
        int i = u >> 3, jb = (u & 7) * 4;
        float a0 = 0.f, a1 = 0.f, a2 = 0.f, a3 = 0.f;
#pragma unroll
        for (int n = 0; n < 49; n++) {
            float s = sc[i][n];
            a0 += s * vs[n][jb + 0];
            a1 += s * vs[n][jb + 1];
            a2 += s * vs[n][jb + 2];
            a3 += s * vs[n][jb + 3];
        }
        int l = (wh * 7 + i / 7) * 56 + ww * 7 + (i % 7);
        long idx = (frame + l) * 192 + h * 32 + jb;
        *reinterpret_cast<uint2*>(O + idx) = make_uint2(pack_h2(a0, a1), pack_h2(a2, a3));
    }
}

// ---------------- temporal attention (fp16 qkv in) -> fp16 out ----------------
__global__ void __launch_bounds__(256) attn_temporal_kernel(const __half* __restrict__ qkv,
                                                            __half* __restrict__ O) {
    const int unit = blockIdx.x * 8 + (threadIdx.x >> 5);
    const int lane = threadIdx.x & 31;
    const int g = unit / 6, h = unit % 6;
    const int b = g / Lv, l = g % Lv;
    const long base0 = ((long)(b * 8) * Lv + l) * 576 + h * 32 + lane;
    const long tstride = (long)Lv * 576;

    float q[8], k[8], v[8];
#pragma unroll
    for (int t = 0; t < 8; t++) {
        long base = base0 + (long)t * tstride;
        q[t] = __half2float(qkv[base]);
        k[t] = __half2float(qkv[base + 192]);
        v[t] = __half2float(qkv[base + 384]);
    }
#pragma unroll
    for (int t1 = 0; t1 < 8; t1++) {
        float s[8];
#pragma unroll
        for (int t2 = 0; t2 < 8; t2++) s[t2] = q[t1] * k[t2];
#pragma unroll
        for (int o = 16; o > 0; o >>= 1) {
#pragma unroll
            for (int t2 = 0; t2 < 8; t2++) s[t2] += __shfl_xor_sync(~0u, s[t2], o);
        }
        float mx = s[0];
#pragma unroll
        for (int t2 = 1; t2 < 8; t2++) mx = fmaxf(mx, s[t2]);
        float sum = 0.f;
#pragma unroll
        for (int t2 = 0; t2 < 8; t2++) { s[t2] = __expf(s[t2] - mx); sum += s[t2]; }
        float inv = 1.0f / sum;
        float o = 0.f;
#pragma unroll
        for (int t2 = 0; t2 < 8; t2++) o += s[t2] * v[t2];
        O[((long)(b * 8 + t1) * Lv + l) * 192 + h * 32 + lane] = __float2half_rn(o * inv);
    }
}

// ---------------- launcher ----------------
extern "C" void kernel_launch(void* const* d_in, const int* in_sizes, int n_in,
                              void* d_out, int out_size) {
    (void)in_sizes; (void)n_in;
    const float* x        = (const float*)d_in[0];
    const float* norm1_g  = (const float*)d_in[2];
    const float* norm1_b  = (const float*)d_in[3];
    const float* qkv_w    = (const float*)d_in[4];
    const float* qkv_b    = (const float*)d_in[5];
    const float* proj_sp_w = (const float*)d_in[6];
    const float* proj_sp_b = (const float*)d_in[7];
    const float* proj_t_w = (const float*)d_in[8];
    const float* proj_t_b = (const float*)d_in[9];
    const float* norm2_g  = (const float*)d_in[10];
    const float* norm2_b  = (const float*)d_in[11];
    const float* te_fc1_w = (const float*)d_in[12];
    const float* te_fc1_b = (const float*)d_in[13];
    const float* te_fc2_w = (const float*)d_in[14];
    const float* te_fc2_b = (const float*)d_in[15];
    const float* sp_fc1_w = (const float*)d_in[16];
    const float* sp_fc1_b = (const float*)d_in[17];
    const float* sp_fc2_w = (const float*)d_in[18];
    const float* sp_fc2_b = (const float*)d_in[19];
    const float* fuse_w   = (const float*)d_in[20];
    const float* fuse_b   = (const float*)d_in[21];

    float* out = (float*)d_out;
    float *xt, *xsp;
    if ((long)out_size >= 3 * MCl) {
        xt = out + MCl;
        xsp = out + 2 * MCl;
    } else {
        void* p;
        cudaGetSymbolAddress(&p, g_xt_fb);  xt = (float*)p;
        cudaGetSymbolAddress(&p, g_xsp_fb); xsp = (float*)p;
    }
    void* p;
    cudaGetSymbolAddress(&p, g_qkv);  __half* qkv = (__half*)p;
    cudaGetSymbolAddress(&p, g_a);    __half* a = (__half*)p;
    cudaGetSymbolAddress(&p, g_osp);  __half* osp = (__half*)p;
    cudaGetSymbolAddress(&p, g_ot);   __half* ot = (__half*)p;
    cudaGetSymbolAddress(&p, g_h);    __half* hb = (__half*)p;
    cudaGetSymbolAddress(&p, g_cat);  __half* cat = (__half*)p;
    cudaGetSymbolAddress(&p, g_whi);  __half* whi = (__half*)p;

    cudaFuncSetAttribute(mma_gemm<192, 1>, cudaFuncAttributeMaxDynamicSharedMemorySize, DSMEM);
    cudaFuncSetAttribute(mma_gemm<192, 2>, cudaFuncAttributeMaxDynamicSharedMemorySize, DSMEM);
    cudaFuncSetAttribute(mma_gemm<192, 4>, cudaFuncAttributeMaxDynamicSharedMemorySize, DSMEM);
    cudaFuncSetAttribute(mma_gemm<768, 2>, cudaFuncAttributeMaxDynamicSharedMemorySize, DSMEM);
    cudaFuncSetAttribute(mma_gemm<384, 0>, cudaFuncAttributeMaxDynamicSharedMemorySize, DSMEM);

    const int MT = Mv / 128;  // 1568

    w_conv_all_kernel<<<(847872 + 255) / 256, 256>>>(
        qkv_w, proj_sp_w, proj_t_w, te_fc1_w, te_fc2_w, sp_fc1_w, sp_fc2_w, fuse_w, whi);
    ln_apply_kernel<<<Mv / 8, 256>>>(x, norm1_g, norm1_b, a);
    // QKV (N=576) -> fp16
    mma_gemm<192, 1><<<dim3(MT, 6), 256, DSMEM>>>(
        a, whi + WO_QKV, qkv_b, nullptr, nullptr, qkv, nullptr, 0, 576);
    // attention
    attn_spatial_kernel<<<4096 * 6, 128>>>(qkv, osp);
    attn_temporal_kernel<<<(Bv * Lv * 6) / 8, 256>>>(qkv, ot);
    // proj + residual
    mma_gemm<192, 2><<<dim3(MT, 2), 256, DSMEM>>>(
        osp, whi + WO_PSP, proj_sp_b, x, xsp, nullptr, nullptr, 0, 192);
    mma_gemm<192, 2><<<dim3(MT, 2), 256, DSMEM>>>(
        ot, whi + WO_PT, proj_t_b, x, xt, nullptr, nullptr, 0, 192);
    // temporal MLP (fc2 also emits concat slot 0)
    ln_apply_kernel<<<Mv / 8, 256>>>(xt, norm2_g, norm2_b, a);
    mma_gemm<192, 4><<<dim3(MT, 8), 256, DSMEM>>>(
        a, whi + WO_TF1, te_fc1_b, nullptr, nullptr, hb, nullptr, 0, HIDv);
    mma_gemm<768, 2><<<dim3(MT, 2), 256, DSMEM>>>(
        hb, whi + WO_TF2, te_fc2_b, xt, xt, nullptr, cat, 0, 192);
    // spatial MLP (fc2 emits concat slot 192)
    ln_apply_kernel<<<Mv / 8, 256>>>(xsp, norm2_g, norm2_b, a);
    mma_gemm<192, 4><<<dim3(MT, 8), 256, DSMEM>>>(
        a, whi + WO_SF1, sp_fc1_b, nullptr, nullptr, hb, nullptr, 0, HIDv);
    mma_gemm<768, 2><<<dim3(MT, 2), 256, DSMEM>>>(
        hb, whi + WO_SF2, sp_fc2_b, xsp, xsp, nullptr, cat, 192, 192);
    // fuse
    mma_gemm<384, 0><<<dim3(MT, 2), 256, DSMEM>>>(
        cat, whi + WO_FUSE, fuse_b, nullptr, out, nullptr, nullptr, 0, 192);
}